// round 5
// baseline (speedup 1.0000x reference)
#include <cuda_runtime.h>

// ---------------- problem constants ----------------
#define B_    64
#define T_    24
#define N_    300
#define F_    16
#define D_    64
#define C_    128
#define H_    12
#define BT_   (B_ * T_)        // 1536
#define BTN_  (BT_ * N_)       // 460800
#define ND_   (N_ * D_)        // 19200
#define Q_    (BT_ * D_)       // 98304  (bt*64+d axis)
#define KCONV_ (3 * ND_)       // 57600

#define CSK    24              // conv1 split-K (57600/24 = 2400, within one k-shift)
#define CKCH   2400
#define MLP1_SK   8
#define MLP1_KCH  2416

typedef unsigned long long u64;

__device__ __forceinline__ u64 ffma2(u64 a, u64 b, u64 c) {
    u64 d;
    asm("fma.rn.f32x2 %0, %1, %2, %3;" : "=l"(d) : "l"(a), "l"(b), "l"(c));
    return d;
}
__device__ __forceinline__ float2 upk(u64 v) {
    float2 r;
    asm("mov.b64 {%0, %1}, %2;" : "=f"(r.x), "=f"(r.y) : "l"(v));
    return r;
}

// ---------------- scratch (device globals; no allocation) ----------------
__device__ float g_S[(size_t)N_ * Q_];              // S buffer, (n, q=bt*64+d) layout
__device__ float g_Hh[(size_t)BTN_ * D_];           // h buffer (layout varies by stage)
__device__ float g_w1p[KCONV_ * C_];                // repacked conv_w1 (k,cin,c)
__device__ float g_y1part[CSK * BT_ * C_];          // conv1 split-K partials (ks, bt, c)
__device__ float g_pooled[B_ * C_];
__device__ float g_z1part[MLP1_SK * B_ * 512];
__device__ float g_z2[B_ * 256];

// ---------------- K0: repack conv_w1 (c,cin,k) -> (k,cin,c) ----------------
__global__ void k_repack(const float* __restrict__ w1)
{
    __shared__ float s[32][97];
    const int cin0 = blockIdx.x * 32;
    const int c0   = blockIdx.y * 32;
    const int tid  = threadIdx.x;
    for (int i = tid; i < 32 * 96; i += 256) {
        int cl = i / 96, j = i - cl * 96;
        s[cl][j] = w1[(c0 + cl) * 57600 + cin0 * 3 + j];
    }
    __syncthreads();
    for (int i = tid; i < 3 * 32 * 32; i += 256) {
        int cl  = i & 31;
        int cil = (i >> 5) & 31;
        int k   = i >> 10;
        g_w1p[(k * ND_ + cin0 + cil) * C_ + c0 + cl] = s[cl][cil * 3 + k];
    }
}

// ---------------- K1: S1 = x @ gcn_w1, written TRANSPOSED to (n, q) ----------------
__global__ void k_xw1(const float* __restrict__ x, const float* __restrict__ w)
{
    __shared__ float ws[16 * 64];
    __shared__ float xs[64 * 16];
    const int tid  = threadIdx.x;
    const int row0 = blockIdx.x * 64;    // row = bt*300 + n
    for (int i = tid; i < 1024; i += 256) ws[i] = w[i];
    for (int i = tid; i < 1024; i += 256) xs[i] = x[row0 * 16 + i];
    __syncthreads();
    for (int i = tid; i < 4096; i += 256) {
        int r = i >> 6, d = i & 63;
        float acc = 0.f;
        #pragma unroll
        for (int k = 0; k < 16; k++) acc = fmaf(xs[r * 16 + k], ws[k * 64 + d], acc);
        int row = row0 + r;
        int bt = row / N_, n = row - bt * N_;
        g_S[(size_t)n * Q_ + bt * 64 + d] = acc;
    }
}

// ---------------- K2: big adj GEMM, f32x2 microkernel ----------------
// C[m, q] = relu( sum_k adj[m,k] * Bsrc[k, q] + bias[q%64] )
// TRANS=0: store C[m,q] contiguous (n, q).  TRANS=1: store to (bt, m*64+d).
template<int TRANS>
__global__ __launch_bounds__(256, 2) void k_adjmm(const float* __restrict__ A,
                                                  const float* __restrict__ Bsrc,
                                                  const float* __restrict__ bias,
                                                  float* __restrict__ Out)
{
    __shared__ __align__(16) float As[16][260];   // duplicated pairs: As[k][2m]=As[k][2m+1]
    __shared__ __align__(16) float Bs[16][128];
    const int q0 = blockIdx.x * 128;
    const int m0 = blockIdx.y * 128;
    const int tid = threadIdx.x;
    const int tx = tid & 15, ty = tid >> 4;
    u64 acc[8][4] = {};
    for (int k0 = 0; k0 < N_; k0 += 16) {
        #pragma unroll
        for (int i = tid; i < 2048; i += 256) {
            int m = i >> 4, k = i & 15;
            int gm = m0 + m, gk = k0 + k;
            float v = (gm < N_ && gk < N_) ? A[gm * N_ + gk] : 0.f;
            *(float2*)&As[k][2 * m] = make_float2(v, v);
        }
        #pragma unroll
        for (int i = tid; i < 2048; i += 256) {
            int k = i >> 7, n = i & 127;
            int gk = k0 + k;
            Bs[k][n] = (gk < N_) ? Bsrc[(size_t)gk * Q_ + q0 + n] : 0.f;
        }
        __syncthreads();
        #pragma unroll
        for (int k = 0; k < 16; k++) {
            const ulonglong2* ap = (const ulonglong2*)&As[k][ty * 16];
            const ulonglong2* bp = (const ulonglong2*)&Bs[k][tx * 8];
            ulonglong2 A0 = ap[0], A1 = ap[1], A2 = ap[2], A3 = ap[3];
            ulonglong2 B0 = bp[0], B1 = bp[1];
            u64 av[8] = {A0.x, A0.y, A1.x, A1.y, A2.x, A2.y, A3.x, A3.y};
            u64 bv[4] = {B0.x, B0.y, B1.x, B1.y};
            #pragma unroll
            for (int i2 = 0; i2 < 8; i2++)
                #pragma unroll
                for (int j = 0; j < 4; j++)
                    acc[i2][j] = ffma2(av[i2], bv[j], acc[i2][j]);
        }
        __syncthreads();
    }
    const int qb = q0 + tx * 8;
    const int d0 = qb & 63;
    float bb[8];
    #pragma unroll
    for (int j = 0; j < 8; j++) bb[j] = bias[d0 + j];
    #pragma unroll
    for (int i2 = 0; i2 < 8; i2++) {
        int m = m0 + ty * 8 + i2;
        if (m < N_) {
            float r[8];
            #pragma unroll
            for (int j = 0; j < 4; j++) {
                float2 p = upk(acc[i2][j]);
                r[2 * j]     = fmaxf(p.x + bb[2 * j], 0.f);
                r[2 * j + 1] = fmaxf(p.y + bb[2 * j + 1], 0.f);
            }
            float* op;
            if (TRANS) {
                int bt = qb >> 6;
                op = Out + (size_t)bt * ND_ + m * 64 + d0;
            } else {
                op = Out + (size_t)m * Q_ + qb;
            }
            *(float4*)op       = make_float4(r[0], r[1], r[2], r[3]);
            *(float4*)(op + 4) = make_float4(r[4], r[5], r[6], r[7]);
        }
    }
}

// ---------------- K3: S2 = h1 @ gcn_w2 (460800 x 64 x 64), f32x2 --------------------
// h1 rows rr = n*1536+bt live in g_Hh[rr*64 + e]; output same row layout into g_S.
__global__ __launch_bounds__(256, 2) void k_hw2(const float* __restrict__ w)
{
    __shared__ __align__(16) float As[16][260];
    __shared__ __align__(16) float Bs[16][64];
    const int r0 = blockIdx.x * 128;
    const int tid = threadIdx.x;
    const int tx = tid & 15, ty = tid >> 4;
    u64 acc[8][2] = {};
    for (int k0 = 0; k0 < D_; k0 += 16) {
        #pragma unroll
        for (int i = tid; i < 2048; i += 256) {
            int m = i >> 4, k = i & 15;
            float v = g_Hh[(size_t)(r0 + m) * 64 + k0 + k];
            *(float2*)&As[k][2 * m] = make_float2(v, v);
        }
        #pragma unroll
        for (int i = tid; i < 1024; i += 256) {
            int k = i >> 6, n = i & 63;
            Bs[k][n] = w[(k0 + k) * 64 + n];
        }
        __syncthreads();
        #pragma unroll
        for (int k = 0; k < 16; k++) {
            const ulonglong2* ap = (const ulonglong2*)&As[k][ty * 16];
            const ulonglong2* bp = (const ulonglong2*)&Bs[k][tx * 4];
            ulonglong2 A0 = ap[0], A1 = ap[1], A2 = ap[2], A3 = ap[3];
            ulonglong2 B0 = bp[0];
            u64 av[8] = {A0.x, A0.y, A1.x, A1.y, A2.x, A2.y, A3.x, A3.y};
            u64 bv[2] = {B0.x, B0.y};
            #pragma unroll
            for (int i2 = 0; i2 < 8; i2++)
                #pragma unroll
                for (int j = 0; j < 2; j++)
                    acc[i2][j] = ffma2(av[i2], bv[j], acc[i2][j]);
        }
        __syncthreads();
    }
    #pragma unroll
    for (int i2 = 0; i2 < 8; i2++) {
        float2 p0 = upk(acc[i2][0]), p1 = upk(acc[i2][1]);
        *(float4*)&g_S[(size_t)(r0 + ty * 8 + i2) * 64 + tx * 4] =
            make_float4(p0.x, p0.y, p1.x, p1.y);
    }
}

// ---------------- K4: conv1 split-K GEMM, f32x2 (M=1536, N=128, Kchunk=2400) --------
__global__ __launch_bounds__(256, 2) void k_conv1()
{
    __shared__ __align__(16) float As[16][260];
    __shared__ __align__(16) float Bs[16][128];
    __shared__ int rowOff[128];
    const int bt0 = blockIdx.x * 128;
    const int ks  = blockIdx.y;
    const int kb0 = ks * CKCH;
    const int kshift = kb0 / ND_;
    const int cin0 = kb0 - kshift * ND_;
    const int tid = threadIdx.x;
    const int tx = tid & 15, ty = tid >> 4;
    if (tid < 128) {
        int bt = bt0 + tid;
        int b = bt / T_, t = bt - b * T_;
        int tp = t + kshift - 1;
        rowOff[tid] = (tp >= 0 && tp < T_) ? ((b * T_ + tp) * ND_ + cin0) : -1;
    }
    __syncthreads();
    u64 acc[8][4] = {};
    for (int k0 = 0; k0 < CKCH; k0 += 16) {
        #pragma unroll
        for (int i = tid; i < 2048; i += 256) {
            int m = i >> 4, k = i & 15;
            int off = rowOff[m];
            float v = (off >= 0) ? g_Hh[off + k0 + k] : 0.f;
            *(float2*)&As[k][2 * m] = make_float2(v, v);
        }
        #pragma unroll
        for (int i = tid; i < 2048; i += 256) {
            int k = i >> 7, n = i & 127;
            Bs[k][n] = g_w1p[(kb0 + k0 + k) * C_ + n];
        }
        __syncthreads();
        #pragma unroll
        for (int k = 0; k < 16; k++) {
            const ulonglong2* ap = (const ulonglong2*)&As[k][ty * 16];
            const ulonglong2* bp = (const ulonglong2*)&Bs[k][tx * 8];
            ulonglong2 A0 = ap[0], A1 = ap[1], A2 = ap[2], A3 = ap[3];
            ulonglong2 B0 = bp[0], B1 = bp[1];
            u64 av[8] = {A0.x, A0.y, A1.x, A1.y, A2.x, A2.y, A3.x, A3.y};
            u64 bv[4] = {B0.x, B0.y, B1.x, B1.y};
            #pragma unroll
            for (int i2 = 0; i2 < 8; i2++)
                #pragma unroll
                for (int j = 0; j < 4; j++)
                    acc[i2][j] = ffma2(av[i2], bv[j], acc[i2][j]);
        }
        __syncthreads();
    }
    #pragma unroll
    for (int i2 = 0; i2 < 8; i2++) {
        int bt = bt0 + ty * 8 + i2;
        float* op = g_y1part + ((size_t)ks * BT_ + bt) * C_ + tx * 8;
        float2 p0 = upk(acc[i2][0]), p1 = upk(acc[i2][1]);
        float2 p2 = upk(acc[i2][2]), p3 = upk(acc[i2][3]);
        *(float4*)op       = make_float4(p0.x, p0.y, p1.x, p1.y);
        *(float4*)(op + 4) = make_float4(p2.x, p2.y, p3.x, p3.y);
    }
}

// ---------------- K5: conv2 + relu + temporal mean-pool ----------------
__global__ void k_conv2pool(const float* __restrict__ cb1,
                            const float* __restrict__ w2,
                            const float* __restrict__ cb2)
{
    __shared__ float ys[C_ * 26];     // [c1][26] padded t
    const int b = blockIdx.x;
    const int tid = threadIdx.x;
    for (int i = tid; i < C_ * T_; i += 256) {
        int c = i & 127, t = i >> 7;
        float v = cb1[c];
        #pragma unroll
        for (int s = 0; s < CSK; s++)
            v += g_y1part[((size_t)s * BT_ + b * T_ + t) * C_ + c];
        ys[c * 26 + t + 1] = fmaxf(v, 0.f);
    }
    if (tid < C_) { ys[tid * 26 + 0] = 0.f; ys[tid * 26 + 25] = 0.f; }
    __syncthreads();

    const int c = tid >> 1;
    const int half = tid & 1;
    const int tbase = half * 12;
    const float bias2 = cb2[c];
    const float* wrow = w2 + c * (C_ * 3);
    float acc[12];
    #pragma unroll
    for (int tt = 0; tt < 12; tt++) acc[tt] = bias2;
    for (int c1 = 0; c1 < C_; c1++) {
        float w0 = wrow[c1 * 3 + 0];
        float w1 = wrow[c1 * 3 + 1];
        float w2v = wrow[c1 * 3 + 2];
        float yv[14];
        #pragma unroll
        for (int idx = 0; idx < 14; idx++) yv[idx] = ys[c1 * 26 + tbase + idx];
        #pragma unroll
        for (int tt = 0; tt < 12; tt++)
            acc[tt] += w0 * yv[tt] + w1 * yv[tt + 1] + w2v * yv[tt + 2];
    }
    float s = 0.f;
    #pragma unroll
    for (int tt = 0; tt < 12; tt++) s += fmaxf(acc[tt], 0.f);
    s += __shfl_xor_sync(0xffffffffu, s, 1);
    if (half == 0) g_pooled[b * C_ + c] = s * (1.f / 24.f);
}

// ---------------- K6: MLP1 split-K, partials out (64 x 19328 x 512) ----------------
__global__ void k_mlp1(const float* __restrict__ w)
{
    const int n0  = blockIdx.x * 64;
    const int kc0 = blockIdx.y * MLP1_KCH;
    __shared__ float Ast[16][68];
    __shared__ float Bs[16][68];
    const int tid = threadIdx.x;
    const int tx = tid & 15, ty = tid >> 4;
    float acc[4][4] = {};
    for (int k0 = 0; k0 < MLP1_KCH; k0 += 16) {
        for (int i = tid; i < 1024; i += 256) {
            int r = i >> 4, k = i & 15;
            int kg = kc0 + k0 + k;
            float v;
            if (kg < ND_) v = g_Hh[(size_t)(r * T_ + (T_ - 1)) * ND_ + kg];
            else          v = g_pooled[r * C_ + (kg - ND_)];
            Ast[k][r] = v;
        }
        for (int i = tid; i < 1024; i += 256) {
            int k = i >> 6, d = i & 63;
            Bs[k][d] = w[(size_t)(kc0 + k0 + k) * 512 + n0 + d];
        }
        __syncthreads();
        #pragma unroll
        for (int k = 0; k < 16; k++) {
            float4 a4 = *reinterpret_cast<const float4*>(&Ast[k][ty * 4]);
            float4 b4 = *reinterpret_cast<const float4*>(&Bs[k][tx * 4]);
            float a[4] = {a4.x, a4.y, a4.z, a4.w};
            float b[4] = {b4.x, b4.y, b4.z, b4.w};
            #pragma unroll
            for (int i = 0; i < 4; i++)
                #pragma unroll
                for (int j = 0; j < 4; j++) acc[i][j] = fmaf(a[i], b[j], acc[i][j]);
        }
        __syncthreads();
    }
    const int ks = blockIdx.y;
    #pragma unroll
    for (int i = 0; i < 4; i++)
        #pragma unroll
        for (int j = 0; j < 4; j++)
            g_z1part[(ks * B_ + ty * 4 + i) * 512 + n0 + tx * 4 + j] = acc[i][j];
}

// ---------------- K7: MLP2  z2 = relu(relu(z1)@w2 + b2)  (64 x 512 x 256) ----------
__global__ void k_mlp2(const float* __restrict__ mb1, const float* __restrict__ w,
                       const float* __restrict__ mb2)
{
    const int n0 = blockIdx.x * 64;
    __shared__ float Ast[16][68];
    __shared__ float Bs[16][68];
    const int tid = threadIdx.x;
    const int tx = tid & 15, ty = tid >> 4;
    float acc[4][4] = {};
    for (int k0 = 0; k0 < 512; k0 += 16) {
        for (int i = tid; i < 1024; i += 256) {
            int r = i >> 4, k = i & 15;
            int kg = k0 + k;
            float v = mb1[kg];
            #pragma unroll
            for (int s = 0; s < MLP1_SK; s++) v += g_z1part[(s * B_ + r) * 512 + kg];
            Ast[k][r] = fmaxf(v, 0.f);
        }
        for (int i = tid; i < 1024; i += 256) {
            int k = i >> 6, d = i & 63;
            Bs[k][d] = w[(k0 + k) * 256 + n0 + d];
        }
        __syncthreads();
        #pragma unroll
        for (int k = 0; k < 16; k++) {
            float4 a4 = *reinterpret_cast<const float4*>(&Ast[k][ty * 4]);
            float4 b4 = *reinterpret_cast<const float4*>(&Bs[k][tx * 4]);
            float a[4] = {a4.x, a4.y, a4.z, a4.w};
            float b[4] = {b4.x, b4.y, b4.z, b4.w};
            #pragma unroll
            for (int i = 0; i < 4; i++)
                #pragma unroll
                for (int j = 0; j < 4; j++) acc[i][j] = fmaf(a[i], b[j], acc[i][j]);
        }
        __syncthreads();
    }
    #pragma unroll
    for (int i = 0; i < 4; i++)
        #pragma unroll
        for (int j = 0; j < 4; j++) {
            int n = n0 + tx * 4 + j;
            g_z2[(ty * 4 + i) * 256 + n] = fmaxf(acc[i][j] + mb2[n], 0.f);
        }
}

// ---------------- K8: MLP3  preds = z2@w3 + b3  (64 x 256 x 3600) -> d_out -----------
__global__ void k_mlp3(const float* __restrict__ w, const float* __restrict__ mb3,
                       float* __restrict__ out)
{
    const int n0 = blockIdx.x * 64;
    __shared__ float Ast[16][68];
    __shared__ float Bs[16][68];
    const int tid = threadIdx.x;
    const int tx = tid & 15, ty = tid >> 4;
    float acc[4][4] = {};
    for (int k0 = 0; k0 < 256; k0 += 16) {
        for (int i = tid; i < 1024; i += 256) {
            int r = i >> 4, k = i & 15;
            Ast[k][r] = g_z2[r * 256 + k0 + k];
        }
        for (int i = tid; i < 1024; i += 256) {
            int k = i >> 6, d = i & 63;
            int n = n0 + d;
            Bs[k][d] = (n < N_ * H_) ? w[(k0 + k) * (N_ * H_) + n] : 0.f;
        }
        __syncthreads();
        #pragma unroll
        for (int k = 0; k < 16; k++) {
            float4 a4 = *reinterpret_cast<const float4*>(&Ast[k][ty * 4]);
            float4 b4 = *reinterpret_cast<const float4*>(&Bs[k][tx * 4]);
            float a[4] = {a4.x, a4.y, a4.z, a4.w};
            float b[4] = {b4.x, b4.y, b4.z, b4.w};
            #pragma unroll
            for (int i = 0; i < 4; i++)
                #pragma unroll
                for (int j = 0; j < 4; j++) acc[i][j] = fmaf(a[i], b[j], acc[i][j]);
        }
        __syncthreads();
    }
    #pragma unroll
    for (int i = 0; i < 4; i++)
        #pragma unroll
        for (int j = 0; j < 4; j++) {
            int n = n0 + tx * 4 + j;
            if (n < N_ * H_)
                out[(ty * 4 + i) * (N_ * H_) + n] = acc[i][j] + mb3[n];
        }
}

// ---------------- launch ----------------
extern "C" void kernel_launch(void* const* d_in, const int* in_sizes, int n_in,
                              void* d_out, int out_size)
{
    const float* x    = (const float*)d_in[0];
    const float* adj  = (const float*)d_in[1];
    const float* gw1  = (const float*)d_in[2];
    const float* gb1  = (const float*)d_in[3];
    const float* gw2  = (const float*)d_in[4];
    const float* gb2  = (const float*)d_in[5];
    const float* cw1  = (const float*)d_in[6];
    const float* cb1  = (const float*)d_in[7];
    const float* cw2  = (const float*)d_in[8];
    const float* cb2  = (const float*)d_in[9];
    const float* mw1  = (const float*)d_in[10];
    const float* mb1  = (const float*)d_in[11];
    const float* mw2  = (const float*)d_in[12];
    const float* mb2  = (const float*)d_in[13];
    const float* mw3  = (const float*)d_in[14];
    const float* mb3  = (const float*)d_in[15];
    float* out = (float*)d_out;

    float* gS;  cudaGetSymbolAddress((void**)&gS,  g_S);
    float* gHh; cudaGetSymbolAddress((void**)&gHh, g_Hh);

    k_repack<<<dim3(ND_ / 32, C_ / 32), 256>>>(cw1);
    k_xw1<<<BTN_ / 64, 256>>>(x, gw1);                      // S1 -> g_S (n,q)
    k_adjmm<0><<<dim3(Q_ / 128, 3), 256>>>(adj, gS, gb1, gHh);   // h1 -> g_Hh (n,q)
    k_hw2<<<BTN_ / 128, 256>>>(gw2);                        // S2 -> g_S (n,q)
    k_adjmm<1><<<dim3(Q_ / 128, 3), 256>>>(adj, gS, gb2, gHh);   // h2 -> g_Hh (bt, n*64+d)
    k_conv1<<<dim3(BT_ / 128, CSK), 256>>>();
    k_conv2pool<<<B_, 256>>>(cb1, cw2, cb2);
    k_mlp1<<<dim3(512 / 64, MLP1_SK), 256>>>(mw1);
    k_mlp2<<<256 / 64, 256>>>(mb1, mw2, mb2);
    k_mlp3<<<(N_ * H_ + 63) / 64, 256>>>(mw3, mb3, out);
}

// round 7
// speedup vs baseline: 1.1864x; 1.1864x over previous
#include <cuda_runtime.h>
#include <cuda_bf16.h>

typedef unsigned int u32;
typedef __nv_bfloat16 bf16;

// ---------------- problem constants ----------------
#define B_    64
#define T_    24
#define N_    300
#define F_    16
#define D_    64
#define C_    128
#define H_    12
#define BT_   (B_ * T_)        // 1536
#define BTN_  (BT_ * N_)       // 460800
#define ND_   (N_ * D_)        // 19200
#define Q_    (BT_ * D_)       // 98304
#define KCONV_ (3 * ND_)       // 57600

#define CSK    24              // conv1 split-K chunks (57600/24 = 2400, within one kshift)
#define CKCH   2400
#define MLP1_SK   8
#define MLP1_KCH  2416

// ---------------- scratch (device globals; no allocation) ----------------
// activations split hi/lo bf16, layout (q = bt*64+d, node) node-contiguous
__device__ bf16 g_Ah[(size_t)Q_ * N_];   // S1 then S2
__device__ bf16 g_Al[(size_t)Q_ * N_];
__device__ bf16 g_Bh[(size_t)Q_ * N_];   // h1 then h2
__device__ bf16 g_Bl[(size_t)Q_ * N_];
__device__ bf16 g_adjh[300 * 304];
__device__ bf16 g_adjl[300 * 304];
__device__ bf16 g_w2th[64 * 64];         // W2^T[d'][d]
__device__ bf16 g_w2tl[64 * 64];
__device__ bf16 g_w1ph[(size_t)C_ * KCONV_];  // [c][kshift*19200 + d*300 + n]
__device__ bf16 g_w1pl[(size_t)C_ * KCONV_];
__device__ float g_y1part[(size_t)CSK * BT_ * C_];
__device__ float g_pooled[B_ * C_];
__device__ float g_z1part[MLP1_SK * B_ * 512];
__device__ float g_z2[B_ * 256];

__device__ __forceinline__ void split_bf16(float v, bf16& h, bf16& l) {
    h = __float2bfloat16(v);
    l = __float2bfloat16(v - __bfloat162float(h));
}

__device__ __forceinline__ void mma_bf16(float c[4], u32 a0, u32 a1, u32 a2, u32 a3,
                                         u32 b0, u32 b1) {
    asm volatile(
        "mma.sync.aligned.m16n8k16.row.col.f32.bf16.bf16.f32 "
        "{%0,%1,%2,%3},{%4,%5,%6,%7},{%8,%9},{%0,%1,%2,%3};\n"
        : "+f"(c[0]), "+f"(c[1]), "+f"(c[2]), "+f"(c[3])
        : "r"(a0), "r"(a1), "r"(a2), "r"(a3), "r"(b0), "r"(b1));
}

// ---------------- P0: split adj and W2^T to bf16 hi/lo ----------------
__global__ void k_prep(const float* __restrict__ adj, const float* __restrict__ w2)
{
    int i = blockIdx.x * 256 + threadIdx.x;
    if (i < 300 * 304) {
        int m = i / 304, k = i - m * 304;
        float v = (k < 300) ? adj[m * 300 + k] : 0.f;
        split_bf16(v, g_adjh[i], g_adjl[i]);
    }
    int j = i - 300 * 304;
    if (j >= 0 && j < 4096) {
        int dp = j >> 6, d = j & 63;
        split_bf16(w2[d * 64 + dp], g_w2th[j], g_w2tl[j]);
    }
}

// ---------------- P1: repack conv_w1 (c, n*64+d, ksh) -> [c][ksh*19200+d*300+n] ----
// grid (128 c, 6 n-blocks of 50)
__global__ void k_repack(const float* __restrict__ w1)
{
    __shared__ float s[50 * 192];
    const int c  = blockIdx.x;
    const int nb = blockIdx.y;
    const int tid = threadIdx.x;
    const float* src = w1 + (size_t)c * 57600 + nb * 9600;
    for (int i = tid; i < 9600; i += 256) s[i] = src[i];
    __syncthreads();
    // j = (ksh*64 + d)*50 + nloc  -> dst k = ksh*19200 + d*300 + nb*50 + nloc
    for (int j = tid; j < 9600; j += 256) {
        int nloc = j % 50;
        int t = j / 50;
        int d = t & 63, ksh = t >> 6;
        float v = s[nloc * 192 + d * 3 + ksh];
        size_t dst = (size_t)c * 57600 + ksh * 19200 + d * 300 + nb * 50 + nloc;
        split_bf16(v, g_w1ph[dst], g_w1pl[dst]);
    }
}

// ---------------- P2: S1 = x @ gcn_w1, write split bf16 to (q, node) ----------------
__global__ void k_xw1(const float* __restrict__ x, const float* __restrict__ w)
{
    __shared__ float ws[16 * 64];
    __shared__ float xs[64 * 16];
    __shared__ bf16 Th[64 * 66], Tl[64 * 66];
    __shared__ int btA[64], nA[64];
    const int tid  = threadIdx.x;
    const int row0 = blockIdx.x * 64;    // row = bt*300 + n
    for (int i = tid; i < 1024; i += 256) ws[i] = w[i];
    for (int i = tid; i < 1024; i += 256) xs[i] = x[row0 * 16 + i];
    if (tid < 64) {
        int r = row0 + tid;
        btA[tid] = r / 300;
        nA[tid]  = r - btA[tid] * 300;
    }
    __syncthreads();
    for (int i = tid; i < 4096; i += 256) {
        int r = i >> 6, d = i & 63;
        float acc = 0.f;
        #pragma unroll
        for (int k = 0; k < 16; k++) acc = fmaf(xs[r * 16 + k], ws[k * 64 + d], acc);
        split_bf16(acc, Th[d * 66 + r], Tl[d * 66 + r]);
    }
    __syncthreads();
    for (int j = tid; j < 4096; j += 256) {
        int rr = j & 63, d = j >> 6;
        size_t addr = ((size_t)btA[rr] * 64 + d) * 300 + nA[rr];
        g_Ah[addr] = Th[d * 66 + rr];
        g_Al[addr] = Tl[d * 66 + rr];
    }
}

// ---------------- K-A: adj GEMM (MMA):  O[q, m] = relu( Σ_k S[q,k]·adj[m,k] + bias[q&63] )
// grid (768 q-tiles, 3 m-tiles), 256 thr = 8 warps (4 m_q x 2 n_m), warp = 32q x 64m
__global__ void k_adjmm(const bf16* __restrict__ Sh, const bf16* __restrict__ Sl,
                        const float* __restrict__ bias,
                        bf16* __restrict__ Oh, bf16* __restrict__ Ol)
{
    __shared__ __align__(16) bf16 sAh[128 * 34], sAl[128 * 34];
    __shared__ __align__(16) bf16 sBh[128 * 34], sBl[128 * 34];
    const int q0 = blockIdx.x * 128;
    const int m0 = blockIdx.y * 128;
    const int tid = threadIdx.x;
    const int warp = tid >> 5, lane = tid & 31;
    const int g = lane >> 2, tig = lane & 3;
    const int wm = warp >> 1, wn = warp & 1;
    float c[2][8][4] = {};

    for (int s = 0; s < 10; s++) {
        const int k0 = s * 32;
        #pragma unroll
        for (int t = 0; t < 8; t++) {
            int i = tid + t * 256;
            int r = i >> 4, p = i & 15;
            int kk = k0 + 2 * p;
            u32 vh = 0, vl = 0;
            if (kk < 300) {
                size_t a = (size_t)(q0 + r) * 300 + kk;
                vh = *(const u32*)&Sh[a];
                vl = *(const u32*)&Sl[a];
            }
            *(u32*)&sAh[r * 34 + 2 * p] = vh;
            *(u32*)&sAl[r * 34 + 2 * p] = vl;
        }
        #pragma unroll
        for (int t = 0; t < 8; t++) {
            int i = tid + t * 256;
            int r = i >> 4, p = i & 15;
            int kk = k0 + 2 * p;
            int m = m0 + r;
            u32 vh = 0, vl = 0;
            if (kk < 300 && m < 300) {
                int a = m * 304 + kk;
                vh = *(const u32*)&g_adjh[a];
                vl = *(const u32*)&g_adjl[a];
            }
            *(u32*)&sBh[r * 34 + 2 * p] = vh;
            *(u32*)&sBl[r * 34 + 2 * p] = vl;
        }
        __syncthreads();
        #pragma unroll
        for (int kb = 0; kb < 32; kb += 16) {
            u32 ah[2][4], al[2][4];
            #pragma unroll
            for (int mi = 0; mi < 2; mi++) {
                int rb = (wm * 32 + mi * 16 + g) * 34 + kb + tig * 2;
                ah[mi][0] = *(const u32*)&sAh[rb];
                ah[mi][1] = *(const u32*)&sAh[rb + 8 * 34];
                ah[mi][2] = *(const u32*)&sAh[rb + 8];
                ah[mi][3] = *(const u32*)&sAh[rb + 8 * 34 + 8];
                al[mi][0] = *(const u32*)&sAl[rb];
                al[mi][1] = *(const u32*)&sAl[rb + 8 * 34];
                al[mi][2] = *(const u32*)&sAl[rb + 8];
                al[mi][3] = *(const u32*)&sAl[rb + 8 * 34 + 8];
            }
            #pragma unroll
            for (int nj = 0; nj < 8; nj++) {
                int nb = (wn * 64 + nj * 8 + g) * 34 + kb + tig * 2;
                u32 bh0 = *(const u32*)&sBh[nb], bh1 = *(const u32*)&sBh[nb + 8];
                u32 bl0 = *(const u32*)&sBl[nb], bl1 = *(const u32*)&sBl[nb + 8];
                #pragma unroll
                for (int mi = 0; mi < 2; mi++) {
                    mma_bf16(c[mi][nj], ah[mi][0], ah[mi][1], ah[mi][2], ah[mi][3], bh0, bh1);
                    mma_bf16(c[mi][nj], ah[mi][0], ah[mi][1], ah[mi][2], ah[mi][3], bl0, bl1);
                    mma_bf16(c[mi][nj], al[mi][0], al[mi][1], al[mi][2], al[mi][3], bh0, bh1);
                }
            }
        }
        __syncthreads();
    }
    // epilogue: bias (by row q), relu, split, store pairs
    #pragma unroll
    for (int mi = 0; mi < 2; mi++) {
        int qlo = q0 + wm * 32 + mi * 16 + g;
        int qhi = qlo + 8;
        float b0 = bias[qlo & 63];
        float b1 = bias[qhi & 63];
        #pragma unroll
        for (int nj = 0; nj < 8; nj++) {
            int m = m0 + wn * 64 + nj * 8 + tig * 2;
            if (m < 300) {
                float v00 = fmaxf(c[mi][nj][0] + b0, 0.f);
                float v01 = fmaxf(c[mi][nj][1] + b0, 0.f);
                float v10 = fmaxf(c[mi][nj][2] + b1, 0.f);
                float v11 = fmaxf(c[mi][nj][3] + b1, 0.f);
                bf16 h0, l0, h1, l1;
                __nv_bfloat162 ph, pl;
                split_bf16(v00, h0, l0); split_bf16(v01, h1, l1);
                ph.x = h0; ph.y = h1; pl.x = l0; pl.y = l1;
                *(__nv_bfloat162*)&Oh[(size_t)qlo * 300 + m] = ph;
                *(__nv_bfloat162*)&Ol[(size_t)qlo * 300 + m] = pl;
                split_bf16(v10, h0, l0); split_bf16(v11, h1, l1);
                ph.x = h0; ph.y = h1; pl.x = l0; pl.y = l1;
                *(__nv_bfloat162*)&Oh[(size_t)qhi * 300 + m] = ph;
                *(__nv_bfloat162*)&Ol[(size_t)qhi * 300 + m] = pl;
            }
        }
    }
}

// ---------------- K-B: hw2 (MMA):  S2[(bt,d'),n] = Σ_d h1[(bt,d),n]·W2[d,d']
// grid 7200 r-tiles of 64 rows r=(bt*300+n); M=r(64), N=d'(64), K=d(64).
// smem-transpose epilogue writes (q,node) layout.  Static smem 33.8 KB.
__global__ void k_hw2mma()
{
    __shared__ __align__(16) char pool[64 * 66 * 2 * 2 + 64 * 66 * 2 * 2];
    bf16* sAh = (bf16*)pool;                       // 64x66
    bf16* sAl = sAh + 64 * 66;
    bf16* sBh = sAl + 64 * 66;                     // 64x66
    bf16* sBl = sBh + 64 * 66;
    bf16* Th  = (bf16*)pool;                       // overlay after compute: 64x66
    bf16* Tl  = Th + 64 * 66;
    __shared__ int btA[64], nA[64];
    const int r0 = blockIdx.x * 64;
    const int tid = threadIdx.x;
    const int warp = tid >> 5, lane = tid & 31;
    const int g = lane >> 2, tig = lane & 3;
    const int wm = warp >> 1, wn = warp & 1;       // wm 0..3 (16 rows), wn 0..1 (32 cols)
    if (tid < 64) {
        int r = r0 + tid;
        btA[tid] = r / 300;
        nA[tid]  = r - btA[tid] * 300;
    }
    __syncthreads();
    // stage A (gather): A[rr][d] = h1[(bt*64+d)*300+n]
    for (int i = tid; i < 4096; i += 256) {
        int kk = i >> 6, rr = i & 63;
        size_t a = ((size_t)btA[rr] * 64 + kk) * 300 + nA[rr];
        sAh[rr * 66 + kk] = g_Bh[a];
        sAl[rr * 66 + kk] = g_Bl[a];
    }
    // stage B: W2T[d'][d]
    for (int i = tid; i < 2048; i += 256) {
        int dp = i >> 5, p = i & 31;
        *(u32*)&sBh[dp * 66 + 2 * p] = *(const u32*)&g_w2th[dp * 64 + 2 * p];
        *(u32*)&sBl[dp * 66 + 2 * p] = *(const u32*)&g_w2tl[dp * 64 + 2 * p];
    }
    __syncthreads();
    float c[4][4] = {};
    #pragma unroll
    for (int kb = 0; kb < 64; kb += 16) {
        u32 ah[4], al[4];
        {
            int rb = (wm * 16 + g) * 66 + kb + tig * 2;
            ah[0] = *(const u32*)&sAh[rb];
            ah[1] = *(const u32*)&sAh[rb + 8 * 66];
            ah[2] = *(const u32*)&sAh[rb + 8];
            ah[3] = *(const u32*)&sAh[rb + 8 * 66 + 8];
            al[0] = *(const u32*)&sAl[rb];
            al[1] = *(const u32*)&sAl[rb + 8 * 66];
            al[2] = *(const u32*)&sAl[rb + 8];
            al[3] = *(const u32*)&sAl[rb + 8 * 66 + 8];
        }
        #pragma unroll
        for (int nj = 0; nj < 4; nj++) {
            int nb = (wn * 32 + nj * 8 + g) * 66 + kb + tig * 2;
            u32 bh0 = *(const u32*)&sBh[nb], bh1 = *(const u32*)&sBh[nb + 8];
            u32 bl0 = *(const u32*)&sBl[nb], bl1 = *(const u32*)&sBl[nb + 8];
            mma_bf16(c[nj], ah[0], ah[1], ah[2], ah[3], bh0, bh1);
            mma_bf16(c[nj], ah[0], ah[1], ah[2], ah[3], bl0, bl1);
            mma_bf16(c[nj], al[0], al[1], al[2], al[3], bh0, bh1);
        }
    }
    __syncthreads();   // done reading A/B smem; overlay transpose buffers
    {
        int rlo = wm * 16 + g;
        #pragma unroll
        for (int nj = 0; nj < 4; nj++) {
            int col = wn * 32 + nj * 8 + tig * 2;
            bf16 h, l;
            split_bf16(c[nj][0], h, l); Th[col * 66 + rlo] = h; Tl[col * 66 + rlo] = l;
            split_bf16(c[nj][1], h, l); Th[(col + 1) * 66 + rlo] = h; Tl[(col + 1) * 66 + rlo] = l;
            split_bf16(c[nj][2], h, l); Th[col * 66 + rlo + 8] = h; Tl[col * 66 + rlo + 8] = l;
            split_bf16(c[nj][3], h, l); Th[(col + 1) * 66 + rlo + 8] = h; Tl[(col + 1) * 66 + rlo + 8] = l;
        }
    }
    __syncthreads();
    for (int i = tid; i < 4096; i += 256) {
        int col = i >> 6, rr = i & 63;
        size_t a = ((size_t)btA[rr] * 64 + col) * 300 + nA[rr];
        g_Ah[a] = Th[col * 66 + rr];
        g_Al[a] = Tl[col * 66 + rr];
    }
}

// ---------------- K-C: conv1 split-K GEMM (MMA), partials fp32 ----------------
// grid (12 bt-tiles, 24 ks). M=bt(128), N=c(128), Kchunk=2400 (k-order ksh,d,n).
__global__ void k_conv1()
{
    __shared__ __align__(16) bf16 sAh[128 * 34], sAl[128 * 34];
    __shared__ __align__(16) bf16 sBh[128 * 34], sBl[128 * 34];
    __shared__ int rowBase[128];
    const int bt0 = blockIdx.x * 128;
    const int ks  = blockIdx.y;
    const int kb0 = ks * CKCH;
    const int ksh = kb0 / ND_;
    const int koff = kb0 - ksh * ND_;      // d*300+n offset within shift
    const int tid = threadIdx.x;
    const int warp = tid >> 5, lane = tid & 31;
    const int g = lane >> 2, tig = lane & 3;
    const int wm = warp >> 1, wn = warp & 1;
    if (tid < 128) {
        int bt = bt0 + tid;
        int b = bt / T_, t = bt - b * T_;
        int tp = t + ksh - 1;
        rowBase[tid] = (tp >= 0 && tp < T_) ? ((b * T_ + tp) * ND_ + koff) : -1;
    }
    __syncthreads();
    float c[2][8][4] = {};
    for (int s = 0; s < CKCH / 32; s++) {
        const int k0 = s * 32;
        #pragma unroll
        for (int t = 0; t < 8; t++) {
            int i = tid + t * 256;
            int r = i >> 4, p = i & 15;
            int base = rowBase[r];
            u32 vh = 0, vl = 0;
            if (base >= 0) {
                size_t a = (size_t)base + k0 + 2 * p;
                vh = *(const u32*)&g_Bh[a];
                vl = *(const u32*)&g_Bl[a];
            }
            *(u32*)&sAh[r * 34 + 2 * p] = vh;
            *(u32*)&sAl[r * 34 + 2 * p] = vl;
        }
        #pragma unroll
        for (int t = 0; t < 8; t++) {
            int i = tid + t * 256;
            int r = i >> 4, p = i & 15;
            size_t a = (size_t)r * 57600 + kb0 + k0 + 2 * p;
            *(u32*)&sBh[r * 34 + 2 * p] = *(const u32*)&g_w1ph[a];
            *(u32*)&sBl[r * 34 + 2 * p] = *(const u32*)&g_w1pl[a];
        }
        __syncthreads();
        #pragma unroll
        for (int kb = 0; kb < 32; kb += 16) {
            u32 ah[2][4], al[2][4];
            #pragma unroll
            for (int mi = 0; mi < 2; mi++) {
                int rb = (wm * 32 + mi * 16 + g) * 34 + kb + tig * 2;
                ah[mi][0] = *(const u32*)&sAh[rb];
                ah[mi][1] = *(const u32*)&sAh[rb + 8 * 34];
                ah[mi][2] = *(const u32*)&sAh[rb + 8];
                ah[mi][3] = *(const u32*)&sAh[rb + 8 * 34 + 8];
                al[mi][0] = *(const u32*)&sAl[rb];
                al[mi][1] = *(const u32*)&sAl[rb + 8 * 34];
                al[mi][2] = *(const u32*)&sAl[rb + 8];
                al[mi][3] = *(const u32*)&sAl[rb + 8 * 34 + 8];
            }
            #pragma unroll
            for (int nj = 0; nj < 8; nj++) {
                int nb = (wn * 64 + nj * 8 + g) * 34 + kb + tig * 2;
                u32 bh0 = *(const u32*)&sBh[nb], bh1 = *(const u32*)&sBh[nb + 8];
                u32 bl0 = *(const u32*)&sBl[nb], bl1 = *(const u32*)&sBl[nb + 8];
                #pragma unroll
                for (int mi = 0; mi < 2; mi++) {
                    mma_bf16(c[mi][nj], ah[mi][0], ah[mi][1], ah[mi][2], ah[mi][3], bh0, bh1);
                    mma_bf16(c[mi][nj], ah[mi][0], ah[mi][1], ah[mi][2], ah[mi][3], bl0, bl1);
                    mma_bf16(c[mi][nj], al[mi][0], al[mi][1], al[mi][2], al[mi][3], bh0, bh1);
                }
            }
        }
        __syncthreads();
    }
    #pragma unroll
    for (int mi = 0; mi < 2; mi++) {
        int btlo = bt0 + wm * 32 + mi * 16 + g;
        int bthi = btlo + 8;
        #pragma unroll
        for (int nj = 0; nj < 8; nj++) {
            int cc = wn * 64 + nj * 8 + tig * 2;
            *(float2*)&g_y1part[((size_t)ks * BT_ + btlo) * C_ + cc] =
                make_float2(c[mi][nj][0], c[mi][nj][1]);
            *(float2*)&g_y1part[((size_t)ks * BT_ + bthi) * C_ + cc] =
                make_float2(c[mi][nj][2], c[mi][nj][3]);
        }
    }
}

// ---------------- K-D: conv2 + relu + temporal mean-pool ----------------
__global__ void k_conv2pool(const float* __restrict__ cb1,
                            const float* __restrict__ w2,
                            const float* __restrict__ cb2)
{
    __shared__ float ys[C_ * 26];
    const int b = blockIdx.x;
    const int tid = threadIdx.x;
    for (int i = tid; i < C_ * T_; i += 256) {
        int c = i & 127, t = i >> 7;
        float v = cb1[c];
        #pragma unroll
        for (int s = 0; s < CSK; s++)
            v += g_y1part[((size_t)s * BT_ + b * T_ + t) * C_ + c];
        ys[c * 26 + t + 1] = fmaxf(v, 0.f);
    }
    if (tid < C_) { ys[tid * 26 + 0] = 0.f; ys[tid * 26 + 25] = 0.f; }
    __syncthreads();

    const int c = tid >> 1;
    const int half = tid & 1;
    const int tbase = half * 12;
    const float bias2 = cb2[c];
    const float* wrow = w2 + c * (C_ * 3);
    float acc[12];
    #pragma unroll
    for (int tt = 0; tt < 12; tt++) acc[tt] = bias2;
    for (int c1 = 0; c1 < C_; c1++) {
        float w0 = wrow[c1 * 3 + 0];
        float w1 = wrow[c1 * 3 + 1];
        float w2v = wrow[c1 * 3 + 2];
        float yv[14];
        #pragma unroll
        for (int idx = 0; idx < 14; idx++) yv[idx] = ys[c1 * 26 + tbase + idx];
        #pragma unroll
        for (int tt = 0; tt < 12; tt++)
            acc[tt] += w0 * yv[tt] + w1 * yv[tt + 1] + w2v * yv[tt + 2];
    }
    float s = 0.f;
    #pragma unroll
    for (int tt = 0; tt < 12; tt++) s += fmaxf(acc[tt], 0.f);
    s += __shfl_xor_sync(0xffffffffu, s, 1);
    if (half == 0) g_pooled[b * C_ + c] = s * (1.f / 24.f);
}

// ---------------- K-E: MLP1 split-K (64 x 19328 x 512), fp32 scalar ----------------
// combined row b = [ h2[b, T-1, n*64+d] (19200) | pooled[b] (128) ]; h2 = hi+lo
__global__ void k_mlp1(const float* __restrict__ w)
{
    const int n0  = blockIdx.x * 64;
    const int kc0 = blockIdx.y * MLP1_KCH;
    __shared__ float Ast[16][68];
    __shared__ float Bs[16][68];
    const int tid = threadIdx.x;
    const int tx = tid & 15, ty = tid >> 4;
    float acc[4][4] = {};
    for (int k0 = 0; k0 < MLP1_KCH; k0 += 16) {
        for (int i = tid; i < 1024; i += 256) {
            int r = i >> 4, k = i & 15;
            int kg = kc0 + k0 + k;
            float v;
            if (kg < ND_) {
                int nn = kg >> 6, d = kg & 63;   // kg = n*64 + d
                size_t a = ((size_t)((r * T_ + (T_ - 1)) * 64 + d)) * 300 + nn;
                v = __bfloat162float(g_Bh[a]) + __bfloat162float(g_Bl[a]);
            } else {
                v = g_pooled[r * C_ + (kg - ND_)];
            }
            Ast[k][r] = v;
        }
        for (int i = tid; i < 1024; i += 256) {
            int k = i >> 6, d = i & 63;
            Bs[k][d] = w[(size_t)(kc0 + k0 + k) * 512 + n0 + d];
        }
        __syncthreads();
        #pragma unroll
        for (int k = 0; k < 16; k++) {
            float4 a4 = *reinterpret_cast<const float4*>(&Ast[k][ty * 4]);
            float4 b4 = *reinterpret_cast<const float4*>(&Bs[k][tx * 4]);
            float a[4] = {a4.x, a4.y, a4.z, a4.w};
            float b[4] = {b4.x, b4.y, b4.z, b4.w};
            #pragma unroll
            for (int i = 0; i < 4; i++)
                #pragma unroll
                for (int j = 0; j < 4; j++) acc[i][j] = fmaf(a[i], b[j], acc[i][j]);
        }
        __syncthreads();
    }
    const int ks = blockIdx.y;
    #pragma unroll
    for (int i = 0; i < 4; i++)
        #pragma unroll
        for (int j = 0; j < 4; j++)
            g_z1part[(ks * B_ + ty * 4 + i) * 512 + n0 + tx * 4 + j] = acc[i][j];
}

// ---------------- K-F: MLP2 ----------------
__global__ void k_mlp2(const float* __restrict__ mb1, const float* __restrict__ w,
                       const float* __restrict__ mb2)
{
    const int n0 = blockIdx.x * 64;
    __shared__ float Ast[16][68];
    __shared__ float Bs[16][68];
    const int tid = threadIdx.x;
    const int tx = tid & 15, ty = tid >> 4;
    float acc[4][4] = {};
    for (int k0 = 0; k0 < 512; k0 += 16) {
        for (int i = tid; i < 1024; i += 256) {
            int r = i >> 4, k = i & 15;
            int kg = k0 + k;
            float v = mb1[kg];
            #pragma unroll
            for (int s = 0; s < MLP1_SK; s++) v += g_z1part[(s * B_ + r) * 512 + kg];
            Ast[k][r] = fmaxf(v, 0.f);
        }
        for (int i = tid; i < 1024; i += 256) {
            int k = i >> 6, d = i & 63;
            Bs[k][d] = w[(k0 + k) * 256 + n0 + d];
        }
        __syncthreads();
        #pragma unroll
        for (int k = 0; k < 16; k++) {
            float4 a4 = *reinterpret_cast<const float4*>(&Ast[k][ty * 4]);
            float4 b4 = *reinterpret_cast<const float4*>(&Bs[k][tx * 4]);
            float a[4] = {a4.x, a4.y, a4.z, a4.w};
            float b[4] = {b4.x, b4.y, b4.z, b4.w};
            #pragma unroll
            for (int i = 0; i < 4; i++)
                #pragma unroll
                for (int j = 0; j < 4; j++) acc[i][j] = fmaf(a[i], b[j], acc[i][j]);
        }
        __syncthreads();
    }
    #pragma unroll
    for (int i = 0; i < 4; i++)
        #pragma unroll
        for (int j = 0; j < 4; j++) {
            int n = n0 + tx * 4 + j;
            g_z2[(ty * 4 + i) * 256 + n] = fmaxf(acc[i][j] + mb2[n], 0.f);
        }
}

// ---------------- K-G: MLP3 -> d_out ----------------
__global__ void k_mlp3(const float* __restrict__ w, const float* __restrict__ mb3,
                       float* __restrict__ out)
{
    const int n0 = blockIdx.x * 64;
    __shared__ float Ast[16][68];
    __shared__ float Bs[16][68];
    const int tid = threadIdx.x;
    const int tx = tid & 15, ty = tid >> 4;
    float acc[4][4] = {};
    for (int k0 = 0; k0 < 256; k0 += 16) {
        for (int i = tid; i < 1024; i += 256) {
            int r = i >> 4, k = i & 15;
            Ast[k][r] = g_z2[r * 256 + k0 + k];
        }
        for (int i = tid; i < 1024; i += 256) {
            int k = i >> 6, d = i & 63;
            int n = n0 + d;
            Bs[k][d] = (n < N_ * H_) ? w[(k0 + k) * (N_ * H_) + n] : 0.f;
        }
        __syncthreads();
        #pragma unroll
        for (int k = 0; k < 16; k++) {
            float4 a4 = *reinterpret_cast<const float4*>(&Ast[k][ty * 4]);
            float4 b4 = *reinterpret_cast<const float4*>(&Bs[k][tx * 4]);
            float a[4] = {a4.x, a4.y, a4.z, a4.w};
            float b[4] = {b4.x, b4.y, b4.z, b4.w};
            #pragma unroll
            for (int i = 0; i < 4; i++)
                #pragma unroll
                for (int j = 0; j < 4; j++) acc[i][j] = fmaf(a[i], b[j], acc[i][j]);
        }
        __syncthreads();
    }
    #pragma unroll
    for (int i = 0; i < 4; i++)
        #pragma unroll
        for (int j = 0; j < 4; j++) {
            int n = n0 + tx * 4 + j;
            if (n < N_ * H_)
                out[(ty * 4 + i) * (N_ * H_) + n] = acc[i][j] + mb3[n];
        }
}

// ---------------- launch ----------------
extern "C" void kernel_launch(void* const* d_in, const int* in_sizes, int n_in,
                              void* d_out, int out_size)
{
    const float* x    = (const float*)d_in[0];
    const float* adj  = (const float*)d_in[1];
    const float* gw1  = (const float*)d_in[2];
    const float* gb1  = (const float*)d_in[3];
    const float* gw2  = (const float*)d_in[4];
    const float* gb2  = (const float*)d_in[5];
    const float* cw1  = (const float*)d_in[6];
    const float* cb1  = (const float*)d_in[7];
    const float* cw2  = (const float*)d_in[8];
    const float* cb2  = (const float*)d_in[9];
    const float* mw1  = (const float*)d_in[10];
    const float* mb1  = (const float*)d_in[11];
    const float* mw2  = (const float*)d_in[12];
    const float* mb2  = (const float*)d_in[13];
    const float* mw3  = (const float*)d_in[14];
    const float* mb3  = (const float*)d_in[15];
    float* out = (float*)d_out;

    bf16 *Ah, *Al, *Bh, *Bl;
    cudaGetSymbolAddress((void**)&Ah, g_Ah);
    cudaGetSymbolAddress((void**)&Al, g_Al);
    cudaGetSymbolAddress((void**)&Bh, g_Bh);
    cudaGetSymbolAddress((void**)&Bl, g_Bl);

    k_prep<<<(300 * 304 + 4096 + 255) / 256, 256>>>(adj, gw2);
    k_repack<<<dim3(C_, 6), 256>>>(cw1);
    k_xw1<<<BTN_ / 64, 256>>>(x, gw1);                       // S1 -> A (split)
    k_adjmm<<<dim3(Q_ / 128, 3), 256>>>(Ah, Al, gb1, Bh, Bl); // h1 -> B
    k_hw2mma<<<BTN_ / 64, 256>>>();                           // S2 -> A
    k_adjmm<<<dim3(Q_ / 128, 3), 256>>>(Ah, Al, gb2, Bh, Bl); // h2 -> B
    k_conv1<<<dim3(BT_ / 128, CSK), 256>>>();
    k_conv2pool<<<B_, 256>>>(cb1, cw2, cb2);
    k_mlp1<<<dim3(512 / 64, MLP1_SK), 256>>>(mw1);
    k_mlp2<<<256 / 64, 256>>>(mb1, mw2, mb2);
    k_mlp3<<<(N_ * H_ + 63) / 64, 256>>>(mw3, mb3, out);
}

// round 8
// speedup vs baseline: 1.5520x; 1.3081x over previous
#include <cuda_runtime.h>
#include <cuda_bf16.h>

typedef unsigned int u32;
typedef __nv_bfloat16 bf16;

// ---------------- problem constants ----------------
#define B_    64
#define T_    24
#define N_    300
#define F_    16
#define D_    64
#define C_    128
#define H_    12
#define BT_   (B_ * T_)        // 1536
#define BTN_  (BT_ * N_)       // 460800
#define ND_   (N_ * D_)        // 19200
#define Q_    (BT_ * D_)       // 98304
#define NP    320              // padded node pitch (zero pad 300..319, 16B-aligned rows)
#define KSH_  (D_ * NP)        // 20480  k-size of one conv shift
#define KCONV (3 * KSH_)       // 61440

#define CSK    24              // conv1 split-K (61440/24 = 2560 = 8 chunks/shift exactly)
#define CKCH   2560
#define MLP1_SK   8
#define MLP1_KCH  2416

// ---------------- scratch (device globals; zero-initialized, no allocation) --------
__device__ bf16 g_Ah[(size_t)Q_ * NP];   // S1 then S2 (hi)
__device__ bf16 g_Al[(size_t)Q_ * NP];
__device__ bf16 g_Bh[(size_t)Q_ * NP];   // h1 then h2 (hi)
__device__ bf16 g_Bl[(size_t)Q_ * NP];
__device__ bf16 g_adjh[384 * NP];        // rows 300..383 stay zero
__device__ bf16 g_adjl[384 * NP];
__device__ bf16 g_w2th[64 * 64];         // W2^T[d'][d]
__device__ bf16 g_w2tl[64 * 64];
__device__ bf16 g_w1ph[(size_t)C_ * KCONV];  // [c][ksh*20480 + d*320 + n]
__device__ bf16 g_w1pl[(size_t)C_ * KCONV];
__device__ __align__(16) bf16 g_zero[32];    // never written: stays zero
__device__ float g_y1part[(size_t)CSK * BT_ * C_];
__device__ float g_pooled[B_ * C_];
__device__ float g_z1part[MLP1_SK * B_ * 512];
__device__ float g_z2[B_ * 256];

__device__ __forceinline__ void split_bf16(float v, bf16& h, bf16& l) {
    h = __float2bfloat16(v);
    l = __float2bfloat16(v - __bfloat162float(h));
}

__device__ __forceinline__ void mma_bf16(float c[4], const u32 a[4], u32 b0, u32 b1) {
    asm volatile(
        "mma.sync.aligned.m16n8k16.row.col.f32.bf16.bf16.f32 "
        "{%0,%1,%2,%3},{%4,%5,%6,%7},{%8,%9},{%0,%1,%2,%3};\n"
        : "+f"(c[0]), "+f"(c[1]), "+f"(c[2]), "+f"(c[3])
        : "r"(a[0]), "r"(a[1]), "r"(a[2]), "r"(a[3]), "r"(b0), "r"(b1));
}
__device__ __forceinline__ u32 s2u(const void* p) { return (u32)__cvta_generic_to_shared(p); }
__device__ __forceinline__ void ldsm4(u32& r0, u32& r1, u32& r2, u32& r3, u32 a) {
    asm volatile("ldmatrix.sync.aligned.m8n8.x4.shared.b16 {%0,%1,%2,%3},[%4];\n"
                 : "=r"(r0), "=r"(r1), "=r"(r2), "=r"(r3) : "r"(a));
}
__device__ __forceinline__ void cp16(u32 d, const void* s) {
    asm volatile("cp.async.cg.shared.global [%0],[%1],16;\n" :: "r"(d), "l"(s));
}
#define CP_COMMIT() asm volatile("cp.async.commit_group;\n")
#define CP_WAIT1()  asm volatile("cp.async.wait_group 1;\n")
#define CP_WAIT0()  asm volatile("cp.async.wait_group 0;\n")

// ---------------- P0: split adj (pitch 320) and W2^T to bf16 hi/lo ----------------
__global__ void k_prep(const float* __restrict__ adj, const float* __restrict__ w2)
{
    int i = blockIdx.x * 256 + threadIdx.x;
    if (i < 300 * NP) {
        int m = i / NP, k = i - m * NP;
        float v = (k < 300) ? adj[m * 300 + k] : 0.f;
        split_bf16(v, g_adjh[i], g_adjl[i]);
    }
    int j = i - 300 * NP;
    if (j >= 0 && j < 4096) {
        int dp = j >> 6, d = j & 63;
        split_bf16(w2[d * 64 + dp], g_w2th[j], g_w2tl[j]);
    }
}

// ---------------- P1: repack conv_w1 (c, n*64+d, ksh) -> [c][ksh*20480+d*320+n] ----
__global__ void k_repack(const float* __restrict__ w1)
{
    __shared__ float s[50 * 192];
    const int c  = blockIdx.x;
    const int nb = blockIdx.y;
    const int tid = threadIdx.x;
    const float* src = w1 + (size_t)c * 57600 + nb * 9600;
    for (int i = tid; i < 9600; i += 256) s[i] = src[i];
    __syncthreads();
    for (int j = tid; j < 9600; j += 256) {
        int nloc = j % 50;
        int t = j / 50;
        int d = t & 63, ksh = t >> 6;
        float v = s[nloc * 192 + d * 3 + ksh];
        size_t dst = (size_t)c * KCONV + ksh * KSH_ + d * NP + nb * 50 + nloc;
        split_bf16(v, g_w1ph[dst], g_w1pl[dst]);
    }
}

// ---------------- P2: S1 = x @ gcn_w1, write split bf16 to (q, node) pitch 320 ------
__global__ void k_xw1(const float* __restrict__ x, const float* __restrict__ w)
{
    __shared__ float ws[16 * 64];
    __shared__ float xs[64 * 16];
    __shared__ bf16 Th[64 * 66], Tl[64 * 66];
    __shared__ int btA[64], nA[64];
    const int tid  = threadIdx.x;
    const int row0 = blockIdx.x * 64;    // row = bt*300 + n
    for (int i = tid; i < 1024; i += 256) ws[i] = w[i];
    for (int i = tid; i < 1024; i += 256) xs[i] = x[row0 * 16 + i];
    if (tid < 64) {
        int r = row0 + tid;
        btA[tid] = r / 300;
        nA[tid]  = r - btA[tid] * 300;
    }
    __syncthreads();
    for (int i = tid; i < 4096; i += 256) {
        int r = i >> 6, d = i & 63;
        float acc = 0.f;
        #pragma unroll
        for (int k = 0; k < 16; k++) acc = fmaf(xs[r * 16 + k], ws[k * 64 + d], acc);
        split_bf16(acc, Th[d * 66 + r], Tl[d * 66 + r]);
    }
    __syncthreads();
    for (int j = tid; j < 4096; j += 256) {
        int rr = j & 63, d = j >> 6;
        size_t addr = ((size_t)btA[rr] * 64 + d) * NP + nA[rr];
        g_Ah[addr] = Th[d * 66 + rr];
        g_Al[addr] = Tl[d * 66 + rr];
    }
}

// ---------------- K-A: adj GEMM, cp.async double-buffered + ldmatrix ----------------
// O[q, m] = relu( sum_k S[q,k]*adj[m,k] + bias[q&63] ).  grid (768, 3), 256 thr.
// smem rows pitch 40 bf16: cols 0-15 hi-k, 16-31 lo-k, pad.
__global__ __launch_bounds__(256) void k_adjmm(const bf16* __restrict__ Sh,
                                               const bf16* __restrict__ Sl,
                                               const float* __restrict__ bias,
                                               bf16* __restrict__ Oh, bf16* __restrict__ Ol)
{
    __shared__ __align__(16) bf16 sA[2][128 * 40];
    __shared__ __align__(16) bf16 sB[2][128 * 40];
    const int q0 = blockIdx.x * 128, m0 = blockIdx.y * 128;
    const int tid = threadIdx.x, warp = tid >> 5, lane = tid & 31;
    const int g = lane >> 2, tig = lane & 3;
    const int wm = warp >> 1, wn = warp & 1;
    const int grp = lane >> 3, lr = lane & 7;
    const u32 saB = s2u(&sA[0][0]), sbB = s2u(&sB[0][0]);
    const u32 BUF = 128 * 40 * 2;
    u32 aAddr[2];
    #pragma unroll
    for (int mi = 0; mi < 2; mi++) {
        int row = wm * 32 + mi * 16 + (grp & 1) * 8 + lr;
        aAddr[mi] = saB + (row * 40 + (grp >> 1) * 8) * 2;
    }
    const u32 bAddr = sbB + ((wn * 64 + (grp >> 1) * 8 + lr) * 40 + (grp & 1) * 8) * 2;
    const int r_ = tid >> 2, sub_ = tid & 3;
    float c[2][8][4] = {};

    // prologue: chunk 0 into buf 0
    #pragma unroll
    for (int t = 0; t < 2; t++) {
        int r = r_ + t * 64, sub = sub_;
        u32 d = (r * 40 + (sub >> 1) * 16 + (sub & 1) * 8) * 2;
        cp16(saB + d, (sub < 2 ? Sh : Sl) + (size_t)(q0 + r) * NP + (sub & 1) * 8);
        cp16(sbB + d, (sub < 2 ? g_adjh : g_adjl) + (size_t)(m0 + r) * NP + (sub & 1) * 8);
    }
    CP_COMMIT();

    for (int s = 0; s < 20; s++) {
        const int bi = s & 1;
        if (s < 19) {
            const int kk0 = (s + 1) * 16;
            const u32 bo = (bi ^ 1) * BUF;
            #pragma unroll
            for (int t = 0; t < 2; t++) {
                int r = r_ + t * 64, sub = sub_;
                u32 d = bo + (r * 40 + (sub >> 1) * 16 + (sub & 1) * 8) * 2;
                cp16(saB + d, (sub < 2 ? Sh : Sl) + (size_t)(q0 + r) * NP + kk0 + (sub & 1) * 8);
                cp16(sbB + d, (sub < 2 ? g_adjh : g_adjl) + (size_t)(m0 + r) * NP + kk0 + (sub & 1) * 8);
            }
            CP_COMMIT();
            CP_WAIT1();
        } else {
            CP_WAIT0();
        }
        __syncthreads();
        const u32 bo = bi * BUF;
        u32 ah[2][4], al[2][4];
        #pragma unroll
        for (int mi = 0; mi < 2; mi++) {
            ldsm4(ah[mi][0], ah[mi][1], ah[mi][2], ah[mi][3], aAddr[mi] + bo);
            ldsm4(al[mi][0], al[mi][1], al[mi][2], al[mi][3], aAddr[mi] + bo + 32);
        }
        #pragma unroll
        for (int p = 0; p < 4; p++) {
            const u32 ba = bAddr + bo + p * 1280;    // p*16 rows * 80B
            u32 bh[4], bl[4];
            ldsm4(bh[0], bh[1], bh[2], bh[3], ba);
            ldsm4(bl[0], bl[1], bl[2], bl[3], ba + 32);
            #pragma unroll
            for (int mi = 0; mi < 2; mi++) {
                mma_bf16(c[mi][2 * p],     ah[mi], bh[0], bh[1]);
                mma_bf16(c[mi][2 * p],     ah[mi], bl[0], bl[1]);
                mma_bf16(c[mi][2 * p],     al[mi], bh[0], bh[1]);
                mma_bf16(c[mi][2 * p + 1], ah[mi], bh[2], bh[3]);
                mma_bf16(c[mi][2 * p + 1], ah[mi], bl[2], bl[3]);
                mma_bf16(c[mi][2 * p + 1], al[mi], bh[2], bh[3]);
            }
        }
        __syncthreads();
    }
    // epilogue: bias (by q), relu, split, store
    #pragma unroll
    for (int mi = 0; mi < 2; mi++) {
        int qlo = q0 + wm * 32 + mi * 16 + g;
        int qhi = qlo + 8;
        float b0 = bias[qlo & 63];
        float b1 = bias[qhi & 63];
        #pragma unroll
        for (int nj = 0; nj < 8; nj++) {
            int m = m0 + wn * 64 + nj * 8 + tig * 2;
            if (m < 300) {
                float v00 = fmaxf(c[mi][nj][0] + b0, 0.f);
                float v01 = fmaxf(c[mi][nj][1] + b0, 0.f);
                float v10 = fmaxf(c[mi][nj][2] + b1, 0.f);
                float v11 = fmaxf(c[mi][nj][3] + b1, 0.f);
                bf16 h0, l0, h1, l1;
                __nv_bfloat162 ph, pl;
                split_bf16(v00, h0, l0); split_bf16(v01, h1, l1);
                ph.x = h0; ph.y = h1; pl.x = l0; pl.y = l1;
                *(__nv_bfloat162*)&Oh[(size_t)qlo * NP + m] = ph;
                *(__nv_bfloat162*)&Ol[(size_t)qlo * NP + m] = pl;
                split_bf16(v10, h0, l0); split_bf16(v11, h1, l1);
                ph.x = h0; ph.y = h1; pl.x = l0; pl.y = l1;
                *(__nv_bfloat162*)&Oh[(size_t)qhi * NP + m] = ph;
                *(__nv_bfloat162*)&Ol[(size_t)qhi * NP + m] = pl;
            }
        }
    }
}

// ---------------- K-B: hw2 (MMA): S2[(bt,d'),n] = sum_d h1[(bt,d),n]*W2[d,d'] -------
// grid 7200 tiles of 64 rows r=(bt*300+n); scalar-gather A (strided), smem 33.8 KB.
__global__ void k_hw2mma()
{
    __shared__ __align__(16) char pool[64 * 66 * 2 * 2 + 64 * 66 * 2 * 2];
    bf16* sAh = (bf16*)pool;
    bf16* sAl = sAh + 64 * 66;
    bf16* sBh = sAl + 64 * 66;
    bf16* sBl = sBh + 64 * 66;
    bf16* Th  = (bf16*)pool;
    bf16* Tl  = Th + 64 * 66;
    __shared__ int btA[64], nA[64];
    const int r0 = blockIdx.x * 64;
    const int tid = threadIdx.x;
    const int warp = tid >> 5, lane = tid & 31;
    const int g = lane >> 2, tig = lane & 3;
    const int wm = warp >> 1, wn = warp & 1;
    if (tid < 64) {
        int r = r0 + tid;
        btA[tid] = r / 300;
        nA[tid]  = r - btA[tid] * 300;
    }
    __syncthreads();
    for (int i = tid; i < 4096; i += 256) {
        int kk = i >> 6, rr = i & 63;
        size_t a = ((size_t)btA[rr] * 64 + kk) * NP + nA[rr];
        sAh[rr * 66 + kk] = g_Bh[a];
        sAl[rr * 66 + kk] = g_Bl[a];
    }
    for (int i = tid; i < 2048; i += 256) {
        int dp = i >> 5, p = i & 31;
        *(u32*)&sBh[dp * 66 + 2 * p] = *(const u32*)&g_w2th[dp * 64 + 2 * p];
        *(u32*)&sBl[dp * 66 + 2 * p] = *(const u32*)&g_w2tl[dp * 64 + 2 * p];
    }
    __syncthreads();
    float c[4][4] = {};
    #pragma unroll
    for (int kb = 0; kb < 64; kb += 16) {
        u32 ah[4], al[4];
        {
            int rb = (wm * 16 + g) * 66 + kb + tig * 2;
            ah[0] = *(const u32*)&sAh[rb];
            ah[1] = *(const u32*)&sAh[rb + 8 * 66];
            ah[2] = *(const u32*)&sAh[rb + 8];
            ah[3] = *(const u32*)&sAh[rb + 8 * 66 + 8];
            al[0] = *(const u32*)&sAl[rb];
            al[1] = *(const u32*)&sAl[rb + 8 * 66];
            al[2] = *(const u32*)&sAl[rb + 8];
            al[3] = *(const u32*)&sAl[rb + 8 * 66 + 8];
        }
        #pragma unroll
        for (int nj = 0; nj < 4; nj++) {
            int nb = (wn * 32 + nj * 8 + g) * 66 + kb + tig * 2;
            u32 bh0 = *(const u32*)&sBh[nb], bh1 = *(const u32*)&sBh[nb + 8];
            u32 bl0 = *(const u32*)&sBl[nb], bl1 = *(const u32*)&sBl[nb + 8];
            mma_bf16(c[nj], ah, bh0, bh1);
            mma_bf16(c[nj], ah, bl0, bl1);
            mma_bf16(c[nj], al, bh0, bh1);
        }
    }
    __syncthreads();
    {
        int rlo = wm * 16 + g;
        #pragma unroll
        for (int nj = 0; nj < 4; nj++) {
            int col = wn * 32 + nj * 8 + tig * 2;
            bf16 h, l;
            split_bf16(c[nj][0], h, l); Th[col * 66 + rlo] = h; Tl[col * 66 + rlo] = l;
            split_bf16(c[nj][1], h, l); Th[(col + 1) * 66 + rlo] = h; Tl[(col + 1) * 66 + rlo] = l;
            split_bf16(c[nj][2], h, l); Th[col * 66 + rlo + 8] = h; Tl[col * 66 + rlo + 8] = l;
            split_bf16(c[nj][3], h, l); Th[(col + 1) * 66 + rlo + 8] = h; Tl[(col + 1) * 66 + rlo + 8] = l;
        }
    }
    __syncthreads();
    for (int i = tid; i < 4096; i += 256) {
        int col = i >> 6, rr = i & 63;
        size_t a = ((size_t)btA[rr] * 64 + col) * NP + nA[rr];
        g_Ah[a] = Th[col * 66 + rr];
        g_Al[a] = Tl[col * 66 + rr];
    }
}

// ---------------- K-C: conv1 split-K GEMM, cp.async + ldmatrix ----------------------
// grid (12 bt-tiles, 24 ks). M=bt(128), N=c(128), Kchunk=2560 in (ksh,d,n-320) order.
__global__ __launch_bounds__(256) void k_conv1()
{
    __shared__ __align__(16) bf16 sA[2][128 * 40];
    __shared__ __align__(16) bf16 sB[2][128 * 40];
    __shared__ int rowBase[128];
    const int bt0 = blockIdx.x * 128;
    const int ks  = blockIdx.y;
    const int kb0 = ks * CKCH;
    const int ksh = kb0 / KSH_;
    const int koff = kb0 - ksh * KSH_;
    const int tid = threadIdx.x, warp = tid >> 5, lane = tid & 31;
    const int g = lane >> 2, tig = lane & 3;
    const int wm = warp >> 1, wn = warp & 1;
    const int grp = lane >> 3, lr = lane & 7;
    const u32 saB = s2u(&sA[0][0]), sbB = s2u(&sB[0][0]);
    const u32 BUF = 128 * 40 * 2;
    if (tid < 128) {
        int bt = bt0 + tid;
        int b = bt / T_, t = bt - b * T_;
        int tp = t + ksh - 1;
        rowBase[tid] = (tp >= 0 && tp < T_) ? ((b * T_ + tp) * KSH_) : -1;
    }
    __syncthreads();
    u32 aAddr[2];
    #pragma unroll
    for (int mi = 0; mi < 2; mi++) {
        int row = wm * 32 + mi * 16 + (grp & 1) * 8 + lr;
        aAddr[mi] = saB + (row * 40 + (grp >> 1) * 8) * 2;
    }
    const u32 bAddr = sbB + ((wn * 64 + (grp >> 1) * 8 + lr) * 40 + (grp & 1) * 8) * 2;
    const int r_ = tid >> 2, sub_ = tid & 3;
    float c[2][8][4] = {};

    // prologue
    #pragma unroll
    for (int t = 0; t < 2; t++) {
        int r = r_ + t * 64, sub = sub_;
        u32 d = (r * 40 + (sub >> 1) * 16 + (sub & 1) * 8) * 2;
        int base = rowBase[r];
        const bf16* sa = (base >= 0)
            ? (sub < 2 ? g_Bh : g_Bl) + (size_t)base + koff + (sub & 1) * 8
            : g_zero + (sub & 1) * 8;
        cp16(saB + d, sa);
        cp16(sbB + d, (sub < 2 ? g_w1ph : g_w1pl) + (size_t)r * KCONV + kb0 + (sub & 1) * 8);
    }
    CP_COMMIT();

    for (int s = 0; s < CKCH / 16; s++) {
        const int bi = s & 1;
        if (s < CKCH / 16 - 1) {
            const int kk0 = (s + 1) * 16;
            const u32 bo = (bi ^ 1) * BUF;
            #pragma unroll
            for (int t = 0; t < 2; t++) {
                int r = r_ + t * 64, sub = sub_;
                u32 d = bo + (r * 40 + (sub >> 1) * 16 + (sub & 1) * 8) * 2;
                int base = rowBase[r];
                const bf16* sa = (base >= 0)
                    ? (sub < 2 ? g_Bh : g_Bl) + (size_t)base + koff + kk0 + (sub & 1) * 8
                    : g_zero + (sub & 1) * 8;
                cp16(saB + d, sa);
                cp16(sbB + d, (sub < 2 ? g_w1ph : g_w1pl) + (size_t)r * KCONV + kb0 + kk0 + (sub & 1) * 8);
            }
            CP_COMMIT();
            CP_WAIT1();
        } else {
            CP_WAIT0();
        }
        __syncthreads();
        const u32 bo = bi * BUF;
        u32 ah[2][4], al[2][4];
        #pragma unroll
        for (int mi = 0; mi < 2; mi++) {
            ldsm4(ah[mi][0], ah[mi][1], ah[mi][2], ah[mi][3], aAddr[mi] + bo);
            ldsm4(al[mi][0], al[mi][1], al[mi][2], al[mi][3], aAddr[mi] + bo + 32);
        }
        #pragma unroll
        for (int p = 0; p < 4; p++) {
            const u32 ba = bAddr + bo + p * 1280;
            u32 bh[4], bl[4];
            ldsm4(bh[0], bh[1], bh[2], bh[3], ba);
            ldsm4(bl[0], bl[1], bl[2], bl[3], ba + 32);
            #pragma unroll
            for (int mi = 0; mi < 2; mi++) {
                mma_bf16(c[mi][2 * p],     ah[mi], bh[0], bh[1]);
                mma_bf16(c[mi][2 * p],     ah[mi], bl[0], bl[1]);
                mma_bf16(c[mi][2 * p],     al[mi], bh[0], bh[1]);
                mma_bf16(c[mi][2 * p + 1], ah[mi], bh[2], bh[3]);
                mma_bf16(c[mi][2 * p + 1], ah[mi], bl[2], bl[3]);
                mma_bf16(c[mi][2 * p + 1], al[mi], bh[2], bh[3]);
            }
        }
        __syncthreads();
    }
    #pragma unroll
    for (int mi = 0; mi < 2; mi++) {
        int btlo = bt0 + wm * 32 + mi * 16 + g;
        int bthi = btlo + 8;
        #pragma unroll
        for (int nj = 0; nj < 8; nj++) {
            int cc = wn * 64 + nj * 8 + tig * 2;
            *(float2*)&g_y1part[((size_t)ks * BT_ + btlo) * C_ + cc] =
                make_float2(c[mi][nj][0], c[mi][nj][1]);
            *(float2*)&g_y1part[((size_t)ks * BT_ + bthi) * C_ + cc] =
                make_float2(c[mi][nj][2], c[mi][nj][3]);
        }
    }
}

// ---------------- K-D: conv2 + relu + temporal mean-pool ----------------
__global__ void k_conv2pool(const float* __restrict__ cb1,
                            const float* __restrict__ w2,
                            const float* __restrict__ cb2)
{
    __shared__ float ys[C_ * 26];
    const int b = blockIdx.x;
    const int tid = threadIdx.x;
    for (int i = tid; i < C_ * T_; i += 256) {
        int c = i & 127, t = i >> 7;
        float v = cb1[c];
        #pragma unroll
        for (int s = 0; s < CSK; s++)
            v += g_y1part[((size_t)s * BT_ + b * T_ + t) * C_ + c];
        ys[c * 26 + t + 1] = fmaxf(v, 0.f);
    }
    if (tid < C_) { ys[tid * 26 + 0] = 0.f; ys[tid * 26 + 25] = 0.f; }
    __syncthreads();

    const int c = tid >> 1;
    const int half = tid & 1;
    const int tbase = half * 12;
    const float bias2 = cb2[c];
    const float* wrow = w2 + c * (C_ * 3);
    float acc[12];
    #pragma unroll
    for (int tt = 0; tt < 12; tt++) acc[tt] = bias2;
    for (int c1 = 0; c1 < C_; c1++) {
        float w0 = wrow[c1 * 3 + 0];
        float w1 = wrow[c1 * 3 + 1];
        float w2v = wrow[c1 * 3 + 2];
        float yv[14];
        #pragma unroll
        for (int idx = 0; idx < 14; idx++) yv[idx] = ys[c1 * 26 + tbase + idx];
        #pragma unroll
        for (int tt = 0; tt < 12; tt++)
            acc[tt] += w0 * yv[tt] + w1 * yv[tt + 1] + w2v * yv[tt + 2];
    }
    float s = 0.f;
    #pragma unroll
    for (int tt = 0; tt < 12; tt++) s += fmaxf(acc[tt], 0.f);
    s += __shfl_xor_sync(0xffffffffu, s, 1);
    if (half == 0) g_pooled[b * C_ + c] = s * (1.f / 24.f);
}

// ---------------- K-E: MLP1 split-K (64 x 19328 x 512), fp32 scalar ----------------
__global__ void k_mlp1(const float* __restrict__ w)
{
    const int n0  = blockIdx.x * 64;
    const int kc0 = blockIdx.y * MLP1_KCH;
    __shared__ float Ast[16][68];
    __shared__ float Bs[16][68];
    const int tid = threadIdx.x;
    const int tx = tid & 15, ty = tid >> 4;
    float acc[4][4] = {};
    for (int k0 = 0; k0 < MLP1_KCH; k0 += 16) {
        for (int i = tid; i < 1024; i += 256) {
            int r = i >> 4, k = i & 15;
            int kg = kc0 + k0 + k;
            float v;
            if (kg < ND_) {
                int nn = kg >> 6, d = kg & 63;   // kg = n*64 + d
                size_t a = ((size_t)((r * T_ + (T_ - 1)) * 64 + d)) * NP + nn;
                v = __bfloat162float(g_Bh[a]) + __bfloat162float(g_Bl[a]);
            } else {
                v = g_pooled[r * C_ + (kg - ND_)];
            }
            Ast[k][r] = v;
        }
        for (int i = tid; i < 1024; i += 256) {
            int k = i >> 6, d = i & 63;
            Bs[k][d] = w[(size_t)(kc0 + k0 + k) * 512 + n0 + d];
        }
        __syncthreads();
        #pragma unroll
        for (int k = 0; k < 16; k++) {
            float4 a4 = *reinterpret_cast<const float4*>(&Ast[k][ty * 4]);
            float4 b4 = *reinterpret_cast<const float4*>(&Bs[k][tx * 4]);
            float a[4] = {a4.x, a4.y, a4.z, a4.w};
            float b[4] = {b4.x, b4.y, b4.z, b4.w};
            #pragma unroll
            for (int i = 0; i < 4; i++)
                #pragma unroll
                for (int j = 0; j < 4; j++) acc[i][j] = fmaf(a[i], b[j], acc[i][j]);
        }
        __syncthreads();
    }
    const int ks = blockIdx.y;
    #pragma unroll
    for (int i = 0; i < 4; i++)
        #pragma unroll
        for (int j = 0; j < 4; j++)
            g_z1part[(ks * B_ + ty * 4 + i) * 512 + n0 + tx * 4 + j] = acc[i][j];
}

// ---------------- K-F: MLP2 ----------------
__global__ void k_mlp2(const float* __restrict__ mb1, const float* __restrict__ w,
                       const float* __restrict__ mb2)
{
    const int n0 = blockIdx.x * 64;
    __shared__ float Ast[16][68];
    __shared__ float Bs[16][68];
    const int tid = threadIdx.x;
    const int tx = tid & 15, ty = tid >> 4;
    float acc[4][4] = {};
    for (int k0 = 0; k0 < 512; k0 += 16) {
        for (int i = tid; i < 1024; i += 256) {
            int r = i >> 4, k = i & 15;
            int kg = k0 + k;
            float v = mb1[kg];
            #pragma unroll
            for (int s = 0; s < MLP1_SK; s++) v += g_z1part[(s * B_ + r) * 512 + kg];
            Ast[k][r] = fmaxf(v, 0.f);
        }
        for (int i = tid; i < 1024; i += 256) {
            int k = i >> 6, d = i & 63;
            Bs[k][d] = w[(k0 + k) * 256 + n0 + d];
        }
        __syncthreads();
        #pragma unroll
        for (int k = 0; k < 16; k++) {
            float4 a4 = *reinterpret_cast<const float4*>(&Ast[k][ty * 4]);
            float4 b4 = *reinterpret_cast<const float4*>(&Bs[k][tx * 4]);
            float a[4] = {a4.x, a4.y, a4.z, a4.w};
            float b[4] = {b4.x, b4.y, b4.z, b4.w};
            #pragma unroll
            for (int i = 0; i < 4; i++)
                #pragma unroll
                for (int j = 0; j < 4; j++) acc[i][j] = fmaf(a[i], b[j], acc[i][j]);
        }
        __syncthreads();
    }
    #pragma unroll
    for (int i = 0; i < 4; i++)
        #pragma unroll
        for (int j = 0; j < 4; j++) {
            int n = n0 + tx * 4 + j;
            g_z2[(ty * 4 + i) * 256 + n] = fmaxf(acc[i][j] + mb2[n], 0.f);
        }
}

// ---------------- K-G: MLP3 -> d_out ----------------
__global__ void k_mlp3(const float* __restrict__ w, const float* __restrict__ mb3,
                       float* __restrict__ out)
{
    const int n0 = blockIdx.x * 64;
    __shared__ float Ast[16][68];
    __shared__ float Bs[16][68];
    const int tid = threadIdx.x;
    const int tx = tid & 15, ty = tid >> 4;
    float acc[4][4] = {};
    for (int k0 = 0; k0 < 256; k0 += 16) {
        for (int i = tid; i < 1024; i += 256) {
            int r = i >> 4, k = i & 15;
            Ast[k][r] = g_z2[r * 256 + k0 + k];
        }
        for (int i = tid; i < 1024; i += 256) {
            int k = i >> 6, d = i & 63;
            int n = n0 + d;
            Bs[k][d] = (n < N_ * H_) ? w[(k0 + k) * (N_ * H_) + n] : 0.f;
        }
        __syncthreads();
        #pragma unroll
        for (int k = 0; k < 16; k++) {
            float4 a4 = *reinterpret_cast<const float4*>(&Ast[k][ty * 4]);
            float4 b4 = *reinterpret_cast<const float4*>(&Bs[k][tx * 4]);
            float a[4] = {a4.x, a4.y, a4.z, a4.w};
            float b[4] = {b4.x, b4.y, b4.z, b4.w};
            #pragma unroll
            for (int i = 0; i < 4; i++)
                #pragma unroll
                for (int j = 0; j < 4; j++) acc[i][j] = fmaf(a[i], b[j], acc[i][j]);
        }
        __syncthreads();
    }
    #pragma unroll
    for (int i = 0; i < 4; i++)
        #pragma unroll
        for (int j = 0; j < 4; j++) {
            int n = n0 + tx * 4 + j;
            if (n < N_ * H_)
                out[(ty * 4 + i) * (N_ * H_) + n] = acc[i][j] + mb3[n];
        }
}

// ---------------- launch ----------------
extern "C" void kernel_launch(void* const* d_in, const int* in_sizes, int n_in,
                              void* d_out, int out_size)
{
    const float* x    = (const float*)d_in[0];
    const float* adj  = (const float*)d_in[1];
    const float* gw1  = (const float*)d_in[2];
    const float* gb1  = (const float*)d_in[3];
    const float* gw2  = (const float*)d_in[4];
    const float* gb2  = (const float*)d_in[5];
    const float* cw1  = (const float*)d_in[6];
    const float* cb1  = (const float*)d_in[7];
    const float* cw2  = (const float*)d_in[8];
    const float* cb2  = (const float*)d_in[9];
    const float* mw1  = (const float*)d_in[10];
    const float* mb1  = (const float*)d_in[11];
    const float* mw2  = (const float*)d_in[12];
    const float* mb2  = (const float*)d_in[13];
    const float* mw3  = (const float*)d_in[14];
    const float* mb3  = (const float*)d_in[15];
    float* out = (float*)d_out;

    bf16 *Ah, *Al, *Bh, *Bl;
    cudaGetSymbolAddress((void**)&Ah, g_Ah);
    cudaGetSymbolAddress((void**)&Al, g_Al);
    cudaGetSymbolAddress((void**)&Bh, g_Bh);
    cudaGetSymbolAddress((void**)&Bl, g_Bl);

    k_prep<<<(300 * NP + 4096 + 255) / 256, 256>>>(adj, gw2);
    k_repack<<<dim3(C_, 6), 256>>>(cw1);
    k_xw1<<<BTN_ / 64, 256>>>(x, gw1);                        // S1 -> A (split)
    k_adjmm<<<dim3(Q_ / 128, 3), 256>>>(Ah, Al, gb1, Bh, Bl); // h1 -> B
    k_hw2mma<<<BTN_ / 64, 256>>>();                           // S2 -> A
    k_adjmm<<<dim3(Q_ / 128, 3), 256>>>(Ah, Al, gb2, Bh, Bl); // h2 -> B
    k_conv1<<<dim3(BT_ / 128, CSK), 256>>>();
    k_conv2pool<<<B_, 256>>>(cb1, cw2, cb2);
    k_mlp1<<<dim3(512 / 64, MLP1_SK), 256>>>(mw1);
    k_mlp2<<<256 / 64, 256>>>(mb1, mw2, mb2);
    k_mlp3<<<(N_ * H_ + 63) / 64, 256>>>(mw3, mb3, out);
}

// round 9
// speedup vs baseline: 1.6978x; 1.0939x over previous
#include <cuda_runtime.h>
#include <cuda_bf16.h>

typedef unsigned int u32;
typedef __nv_bfloat16 bf16;

// ---------------- problem constants ----------------
#define B_    64
#define T_    24
#define N_    300
#define F_    16
#define D_    64
#define C_    128
#define H_    12
#define BT_   (B_ * T_)        // 1536
#define BTN_  (BT_ * N_)       // 460800
#define ND_   (N_ * D_)        // 19200
#define Q_    (BT_ * D_)       // 98304
#define NP    320              // padded node pitch (zero pad 300..319, 16B-aligned rows)
#define KSH_  (D_ * NP)        // 20480  k-size of one conv shift
#define KCONV (3 * KSH_)       // 61440

#define CSK    24              // conv1 split-K (61440/24 = 2560 = 8 chunks/shift exactly)
#define CKCH   2560
#define MLP1_SK   8
#define MLP1_KCH  2416

// ---------------- scratch (device globals; zero-initialized, no allocation) --------
__device__ bf16 g_Ah[(size_t)Q_ * NP];   // S1 then S2 (hi)
__device__ bf16 g_Al[(size_t)Q_ * NP];
__device__ bf16 g_Bh[(size_t)Q_ * NP];   // h1 then h2 (hi)
__device__ bf16 g_Bl[(size_t)Q_ * NP];
__device__ bf16 g_adjh[384 * NP];        // rows 300..383 stay zero
__device__ bf16 g_adjl[384 * NP];
__device__ bf16 g_w2th[64 * 64];         // W2^T[d'][d]
__device__ bf16 g_w2tl[64 * 64];
__device__ bf16 g_w1ph[(size_t)C_ * KCONV];  // [c][ksh*20480 + d*320 + n]
__device__ bf16 g_w1pl[(size_t)C_ * KCONV];
__device__ __align__(16) bf16 g_zero[32];    // never written: stays zero
__device__ float g_y1part[(size_t)CSK * BT_ * C_];
__device__ float g_pooled[B_ * C_];
__device__ float g_z1part[MLP1_SK * B_ * 512];
__device__ float g_z2[B_ * 256];

__device__ __forceinline__ void split_bf16(float v, bf16& h, bf16& l) {
    h = __float2bfloat16(v);
    l = __float2bfloat16(v - __bfloat162float(h));
}

__device__ __forceinline__ void mma_bf16(float c[4], const u32 a[4], u32 b0, u32 b1) {
    asm volatile(
        "mma.sync.aligned.m16n8k16.row.col.f32.bf16.bf16.f32 "
        "{%0,%1,%2,%3},{%4,%5,%6,%7},{%8,%9},{%0,%1,%2,%3};\n"
        : "+f"(c[0]), "+f"(c[1]), "+f"(c[2]), "+f"(c[3])
        : "r"(a[0]), "r"(a[1]), "r"(a[2]), "r"(a[3]), "r"(b0), "r"(b1));
}
__device__ __forceinline__ u32 s2u(const void* p) { return (u32)__cvta_generic_to_shared(p); }
__device__ __forceinline__ void ldsm4(u32& r0, u32& r1, u32& r2, u32& r3, u32 a) {
    asm volatile("ldmatrix.sync.aligned.m8n8.x4.shared.b16 {%0,%1,%2,%3},[%4];\n"
                 : "=r"(r0), "=r"(r1), "=r"(r2), "=r"(r3) : "r"(a));
}
__device__ __forceinline__ void cp16(u32 d, const void* s) {
    asm volatile("cp.async.cg.shared.global [%0],[%1],16;\n" :: "r"(d), "l"(s));
}
#define CP_COMMIT() asm volatile("cp.async.commit_group;\n")
#define CP_WAIT0()  asm volatile("cp.async.wait_group 0;\n")

// ---------------- P0: split adj (pitch 320) and W2^T to bf16 hi/lo ----------------
__global__ void k_prep(const float* __restrict__ adj, const float* __restrict__ w2)
{
    int i = blockIdx.x * 256 + threadIdx.x;
    if (i < 300 * NP) {
        int m = i / NP, k = i - m * NP;
        float v = (k < 300) ? adj[m * 300 + k] : 0.f;
        split_bf16(v, g_adjh[i], g_adjl[i]);
    }
    int j = i - 300 * NP;
    if (j >= 0 && j < 4096) {
        int dp = j >> 6, d = j & 63;
        split_bf16(w2[d * 64 + dp], g_w2th[j], g_w2tl[j]);
    }
}

// ---------------- P1: repack conv_w1 (c, n*64+d, ksh) -> [c][ksh*20480+d*320+n] ----
__global__ void k_repack(const float* __restrict__ w1)
{
    __shared__ float s[50 * 192];
    const int c  = blockIdx.x;
    const int nb = blockIdx.y;
    const int tid = threadIdx.x;
    const float* src = w1 + (size_t)c * 57600 + nb * 9600;
    for (int i = tid; i < 9600; i += 256) s[i] = src[i];
    __syncthreads();
    for (int j = tid; j < 9600; j += 256) {
        int nloc = j % 50;
        int t = j / 50;
        int d = t & 63, ksh = t >> 6;
        float v = s[nloc * 192 + d * 3 + ksh];
        size_t dst = (size_t)c * KCONV + ksh * KSH_ + d * NP + nb * 50 + nloc;
        split_bf16(v, g_w1ph[dst], g_w1pl[dst]);
    }
}

// ---------------- P2: S1 = x @ gcn_w1, write split bf16 to (q, node) pitch 320 ------
__global__ void k_xw1(const float* __restrict__ x, const float* __restrict__ w)
{
    __shared__ float ws[16 * 64];
    __shared__ float xs[64 * 16];
    __shared__ bf16 Th[64 * 66], Tl[64 * 66];
    __shared__ int btA[64], nA[64];
    const int tid  = threadIdx.x;
    const int row0 = blockIdx.x * 64;    // row = bt*300 + n
    for (int i = tid; i < 1024; i += 256) ws[i] = w[i];
    for (int i = tid; i < 1024; i += 256) xs[i] = x[row0 * 16 + i];
    if (tid < 64) {
        int r = row0 + tid;
        btA[tid] = r / 300;
        nA[tid]  = r - btA[tid] * 300;
    }
    __syncthreads();
    for (int i = tid; i < 4096; i += 256) {
        int r = i >> 6, d = i & 63;
        float acc = 0.f;
        #pragma unroll
        for (int k = 0; k < 16; k++) acc = fmaf(xs[r * 16 + k], ws[k * 64 + d], acc);
        split_bf16(acc, Th[d * 66 + r], Tl[d * 66 + r]);
    }
    __syncthreads();
    for (int j = tid; j < 4096; j += 256) {
        int rr = j & 63, d = j >> 6;
        size_t addr = ((size_t)btA[rr] * 64 + d) * NP + nA[rr];
        g_Ah[addr] = Th[d * 66 + rr];
        g_Al[addr] = Tl[d * 66 + rr];
    }
}

// ---------------- K-A: adj GEMM, cp.async double-buffered + ldmatrix ----------------
// O[q, m] = relu( sum_k S[q,k]*adj[m,k] + bias[q&63] ).  grid (768, 3), 256 thr.
// 2 CTAs/SM; single __syncthreads per chunk (issue next loads after ldsm of current).
__global__ __launch_bounds__(256, 2) void k_adjmm(const bf16* __restrict__ Sh,
                                                  const bf16* __restrict__ Sl,
                                                  const float* __restrict__ bias,
                                                  bf16* __restrict__ Oh, bf16* __restrict__ Ol)
{
    __shared__ __align__(16) bf16 sA[2][128 * 40];
    __shared__ __align__(16) bf16 sB[2][128 * 40];
    const int q0 = blockIdx.x * 128, m0 = blockIdx.y * 128;
    const int tid = threadIdx.x, warp = tid >> 5, lane = tid & 31;
    const int g = lane >> 2, tig = lane & 3;
    const int wm = warp >> 1, wn = warp & 1;
    const int grp = lane >> 3, lr = lane & 7;
    const u32 saB = s2u(&sA[0][0]), sbB = s2u(&sB[0][0]);
    const u32 BUF = 128 * 40 * 2;
    u32 aAddr[2];
    #pragma unroll
    for (int mi = 0; mi < 2; mi++) {
        int row = wm * 32 + mi * 16 + (grp & 1) * 8 + lr;
        aAddr[mi] = saB + (row * 40 + (grp >> 1) * 8) * 2;
    }
    const u32 bAddr = sbB + ((wn * 64 + (grp >> 1) * 8 + lr) * 40 + (grp & 1) * 8) * 2;
    const int r_ = tid >> 2, sub_ = tid & 3;
    float c[2][8][4] = {};

    // prologue: chunk 0 into buf 0
    #pragma unroll
    for (int t = 0; t < 2; t++) {
        int r = r_ + t * 64, sub = sub_;
        u32 d = (r * 40 + (sub >> 1) * 16 + (sub & 1) * 8) * 2;
        cp16(saB + d, (sub < 2 ? Sh : Sl) + (size_t)(q0 + r) * NP + (sub & 1) * 8);
        cp16(sbB + d, (sub < 2 ? g_adjh : g_adjl) + (size_t)(m0 + r) * NP + (sub & 1) * 8);
    }
    CP_COMMIT();

    for (int s = 0; s < 20; s++) {
        const int bi = s & 1;
        CP_WAIT0();
        __syncthreads();
        const u32 bo = bi * BUF;
        // load A fragments of current chunk first
        u32 ah[2][4], al[2][4];
        #pragma unroll
        for (int mi = 0; mi < 2; mi++) {
            ldsm4(ah[mi][0], ah[mi][1], ah[mi][2], ah[mi][3], aAddr[mi] + bo);
            ldsm4(al[mi][0], al[mi][1], al[mi][2], al[mi][3], aAddr[mi] + bo + 32);
        }
        // issue next-chunk loads into the other buffer (flies during MMA below)
        if (s < 19) {
            const int kk0 = (s + 1) * 16;
            const u32 bo2 = (bi ^ 1) * BUF;
            #pragma unroll
            for (int t = 0; t < 2; t++) {
                int r = r_ + t * 64, sub = sub_;
                u32 d = bo2 + (r * 40 + (sub >> 1) * 16 + (sub & 1) * 8) * 2;
                cp16(saB + d, (sub < 2 ? Sh : Sl) + (size_t)(q0 + r) * NP + kk0 + (sub & 1) * 8);
                cp16(sbB + d, (sub < 2 ? g_adjh : g_adjl) + (size_t)(m0 + r) * NP + kk0 + (sub & 1) * 8);
            }
            CP_COMMIT();
        }
        #pragma unroll
        for (int p = 0; p < 4; p++) {
            const u32 ba = bAddr + bo + p * 1280;    // p*16 rows * 80B
            u32 bh[4], bl[4];
            ldsm4(bh[0], bh[1], bh[2], bh[3], ba);
            ldsm4(bl[0], bl[1], bl[2], bl[3], ba + 32);
            #pragma unroll
            for (int mi = 0; mi < 2; mi++) {
                mma_bf16(c[mi][2 * p],     ah[mi], bh[0], bh[1]);
                mma_bf16(c[mi][2 * p],     ah[mi], bl[0], bl[1]);
                mma_bf16(c[mi][2 * p],     al[mi], bh[0], bh[1]);
                mma_bf16(c[mi][2 * p + 1], ah[mi], bh[2], bh[3]);
                mma_bf16(c[mi][2 * p + 1], ah[mi], bl[2], bl[3]);
                mma_bf16(c[mi][2 * p + 1], al[mi], bh[2], bh[3]);
            }
        }
    }
    // epilogue: bias (by q), relu, split, store
    #pragma unroll
    for (int mi = 0; mi < 2; mi++) {
        int qlo = q0 + wm * 32 + mi * 16 + g;
        int qhi = qlo + 8;
        float b0 = bias[qlo & 63];
        float b1 = bias[qhi & 63];
        #pragma unroll
        for (int nj = 0; nj < 8; nj++) {
            int m = m0 + wn * 64 + nj * 8 + tig * 2;
            if (m < 300) {
                float v00 = fmaxf(c[mi][nj][0] + b0, 0.f);
                float v01 = fmaxf(c[mi][nj][1] + b0, 0.f);
                float v10 = fmaxf(c[mi][nj][2] + b1, 0.f);
                float v11 = fmaxf(c[mi][nj][3] + b1, 0.f);
                bf16 h0, l0, h1, l1;
                __nv_bfloat162 ph, pl;
                split_bf16(v00, h0, l0); split_bf16(v01, h1, l1);
                ph.x = h0; ph.y = h1; pl.x = l0; pl.y = l1;
                *(__nv_bfloat162*)&Oh[(size_t)qlo * NP + m] = ph;
                *(__nv_bfloat162*)&Ol[(size_t)qlo * NP + m] = pl;
                split_bf16(v10, h0, l0); split_bf16(v11, h1, l1);
                ph.x = h0; ph.y = h1; pl.x = l0; pl.y = l1;
                *(__nv_bfloat162*)&Oh[(size_t)qhi * NP + m] = ph;
                *(__nv_bfloat162*)&Ol[(size_t)qhi * NP + m] = pl;
            }
        }
    }
}

// ---------------- K-B: hw2 (MMA): S2[(bt,d'),n] = sum_d h1[(bt,d),n]*W2[d,d'] -------
// grid 7200 tiles of 64 rows r=(bt*300+n); scalar-gather A (strided), smem 33.8 KB.
__global__ void k_hw2mma()
{
    __shared__ __align__(16) char pool[64 * 66 * 2 * 2 + 64 * 66 * 2 * 2];
    bf16* sAh = (bf16*)pool;
    bf16* sAl = sAh + 64 * 66;
    bf16* sBh = sAl + 64 * 66;
    bf16* sBl = sBh + 64 * 66;
    bf16* Th  = (bf16*)pool;
    bf16* Tl  = Th + 64 * 66;
    __shared__ int btA[64], nA[64];
    const int r0 = blockIdx.x * 64;
    const int tid = threadIdx.x;
    const int warp = tid >> 5, lane = tid & 31;
    const int g = lane >> 2, tig = lane & 3;
    const int wm = warp >> 1, wn = warp & 1;
    if (tid < 64) {
        int r = r0 + tid;
        btA[tid] = r / 300;
        nA[tid]  = r - btA[tid] * 300;
    }
    __syncthreads();
    for (int i = tid; i < 4096; i += 256) {
        int kk = i >> 6, rr = i & 63;
        size_t a = ((size_t)btA[rr] * 64 + kk) * NP + nA[rr];
        sAh[rr * 66 + kk] = g_Bh[a];
        sAl[rr * 66 + kk] = g_Bl[a];
    }
    for (int i = tid; i < 2048; i += 256) {
        int dp = i >> 5, p = i & 31;
        *(u32*)&sBh[dp * 66 + 2 * p] = *(const u32*)&g_w2th[dp * 64 + 2 * p];
        *(u32*)&sBl[dp * 66 + 2 * p] = *(const u32*)&g_w2tl[dp * 64 + 2 * p];
    }
    __syncthreads();
    float c[4][4] = {};
    #pragma unroll
    for (int kb = 0; kb < 64; kb += 16) {
        u32 ah[4], al[4];
        {
            int rb = (wm * 16 + g) * 66 + kb + tig * 2;
            ah[0] = *(const u32*)&sAh[rb];
            ah[1] = *(const u32*)&sAh[rb + 8 * 66];
            ah[2] = *(const u32*)&sAh[rb + 8];
            ah[3] = *(const u32*)&sAh[rb + 8 * 66 + 8];
            al[0] = *(const u32*)&sAl[rb];
            al[1] = *(const u32*)&sAl[rb + 8 * 66];
            al[2] = *(const u32*)&sAl[rb + 8];
            al[3] = *(const u32*)&sAl[rb + 8 * 66 + 8];
        }
        #pragma unroll
        for (int nj = 0; nj < 4; nj++) {
            int nb = (wn * 32 + nj * 8 + g) * 66 + kb + tig * 2;
            u32 bh0 = *(const u32*)&sBh[nb], bh1 = *(const u32*)&sBh[nb + 8];
            u32 bl0 = *(const u32*)&sBl[nb], bl1 = *(const u32*)&sBl[nb + 8];
            mma_bf16(c[nj], ah, bh0, bh1);
            mma_bf16(c[nj], ah, bl0, bl1);
            mma_bf16(c[nj], al, bh0, bh1);
        }
    }
    __syncthreads();
    {
        int rlo = wm * 16 + g;
        #pragma unroll
        for (int nj = 0; nj < 4; nj++) {
            int col = wn * 32 + nj * 8 + tig * 2;
            bf16 h, l;
            split_bf16(c[nj][0], h, l); Th[col * 66 + rlo] = h; Tl[col * 66 + rlo] = l;
            split_bf16(c[nj][1], h, l); Th[(col + 1) * 66 + rlo] = h; Tl[(col + 1) * 66 + rlo] = l;
            split_bf16(c[nj][2], h, l); Th[col * 66 + rlo + 8] = h; Tl[col * 66 + rlo + 8] = l;
            split_bf16(c[nj][3], h, l); Th[(col + 1) * 66 + rlo + 8] = h; Tl[(col + 1) * 66 + rlo + 8] = l;
        }
    }
    __syncthreads();
    for (int i = tid; i < 4096; i += 256) {
        int col = i >> 6, rr = i & 63;
        size_t a = ((size_t)btA[rr] * 64 + col) * NP + nA[rr];
        g_Ah[a] = Th[col * 66 + rr];
        g_Al[a] = Tl[col * 66 + rr];
    }
}

// ---------------- K-C: conv1 split-K GEMM, cp.async + ldmatrix ----------------------
// grid (12 bt-tiles, 24 ks). M=bt(128), N=c(128), Kchunk=2560 in (ksh,d,n-320) order.
// 2 CTAs/SM; single __syncthreads per chunk.
__global__ __launch_bounds__(256, 2) void k_conv1()
{
    __shared__ __align__(16) bf16 sA[2][128 * 40];
    __shared__ __align__(16) bf16 sB[2][128 * 40];
    __shared__ int rowBase[128];
    const int bt0 = blockIdx.x * 128;
    const int ks  = blockIdx.y;
    const int kb0 = ks * CKCH;
    const int ksh = kb0 / KSH_;
    const int koff = kb0 - ksh * KSH_;
    const int tid = threadIdx.x, warp = tid >> 5, lane = tid & 31;
    const int g = lane >> 2, tig = lane & 3;
    const int wm = warp >> 1, wn = warp & 1;
    const int grp = lane >> 3, lr = lane & 7;
    const u32 saB = s2u(&sA[0][0]), sbB = s2u(&sB[0][0]);
    const u32 BUF = 128 * 40 * 2;
    if (tid < 128) {
        int bt = bt0 + tid;
        int b = bt / T_, t = bt - b * T_;
        int tp = t + ksh - 1;
        rowBase[tid] = (tp >= 0 && tp < T_) ? ((b * T_ + tp) * KSH_) : -1;
    }
    __syncthreads();
    u32 aAddr[2];
    #pragma unroll
    for (int mi = 0; mi < 2; mi++) {
        int row = wm * 32 + mi * 16 + (grp & 1) * 8 + lr;
        aAddr[mi] = saB + (row * 40 + (grp >> 1) * 8) * 2;
    }
    const u32 bAddr = sbB + ((wn * 64 + (grp >> 1) * 8 + lr) * 40 + (grp & 1) * 8) * 2;
    const int r_ = tid >> 2, sub_ = tid & 3;
    const int base_ = rowBase[r_], base64_ = rowBase[r_ + 64];
    float c[2][8][4] = {};

    // prologue
    #pragma unroll
    for (int t = 0; t < 2; t++) {
        int r = r_ + t * 64, sub = sub_;
        u32 d = (r * 40 + (sub >> 1) * 16 + (sub & 1) * 8) * 2;
        int base = t ? base64_ : base_;
        const bf16* sa = (base >= 0)
            ? (sub < 2 ? g_Bh : g_Bl) + (size_t)base + koff + (sub & 1) * 8
            : g_zero + (sub & 1) * 8;
        cp16(saB + d, sa);
        cp16(sbB + d, (sub < 2 ? g_w1ph : g_w1pl) + (size_t)r * KCONV + kb0 + (sub & 1) * 8);
    }
    CP_COMMIT();

    for (int s = 0; s < CKCH / 16; s++) {
        const int bi = s & 1;
        CP_WAIT0();
        __syncthreads();
        const u32 bo = bi * BUF;
        u32 ah[2][4], al[2][4];
        #pragma unroll
        for (int mi = 0; mi < 2; mi++) {
            ldsm4(ah[mi][0], ah[mi][1], ah[mi][2], ah[mi][3], aAddr[mi] + bo);
            ldsm4(al[mi][0], al[mi][1], al[mi][2], al[mi][3], aAddr[mi] + bo + 32);
        }
        if (s < CKCH / 16 - 1) {
            const int kk0 = (s + 1) * 16;
            const u32 bo2 = (bi ^ 1) * BUF;
            #pragma unroll
            for (int t = 0; t < 2; t++) {
                int r = r_ + t * 64, sub = sub_;
                u32 d = bo2 + (r * 40 + (sub >> 1) * 16 + (sub & 1) * 8) * 2;
                int base = t ? base64_ : base_;
                const bf16* sa = (base >= 0)
                    ? (sub < 2 ? g_Bh : g_Bl) + (size_t)base + koff + kk0 + (sub & 1) * 8
                    : g_zero + (sub & 1) * 8;
                cp16(saB + d, sa);
                cp16(sbB + d, (sub < 2 ? g_w1ph : g_w1pl) + (size_t)r * KCONV + kb0 + kk0 + (sub & 1) * 8);
            }
            CP_COMMIT();
        }
        #pragma unroll
        for (int p = 0; p < 4; p++) {
            const u32 ba = bAddr + bo + p * 1280;
            u32 bh[4], bl[4];
            ldsm4(bh[0], bh[1], bh[2], bh[3], ba);
            ldsm4(bl[0], bl[1], bl[2], bl[3], ba + 32);
            #pragma unroll
            for (int mi = 0; mi < 2; mi++) {
                mma_bf16(c[mi][2 * p],     ah[mi], bh[0], bh[1]);
                mma_bf16(c[mi][2 * p],     ah[mi], bl[0], bl[1]);
                mma_bf16(c[mi][2 * p],     al[mi], bh[0], bh[1]);
                mma_bf16(c[mi][2 * p + 1], ah[mi], bh[2], bh[3]);
                mma_bf16(c[mi][2 * p + 1], ah[mi], bl[2], bl[3]);
                mma_bf16(c[mi][2 * p + 1], al[mi], bh[2], bh[3]);
            }
        }
    }
    #pragma unroll
    for (int mi = 0; mi < 2; mi++) {
        int btlo = bt0 + wm * 32 + mi * 16 + g;
        int bthi = btlo + 8;
        #pragma unroll
        for (int nj = 0; nj < 8; nj++) {
            int cc = wn * 64 + nj * 8 + tig * 2;
            *(float2*)&g_y1part[((size_t)ks * BT_ + btlo) * C_ + cc] =
                make_float2(c[mi][nj][0], c[mi][nj][1]);
            *(float2*)&g_y1part[((size_t)ks * BT_ + bthi) * C_ + cc] =
                make_float2(c[mi][nj][2], c[mi][nj][3]);
        }
    }
}

// ---------------- K-D: conv2 + relu + temporal mean-pool ----------------
__global__ void k_conv2pool(const float* __restrict__ cb1,
                            const float* __restrict__ w2,
                            const float* __restrict__ cb2)
{
    __shared__ float ys[C_ * 26];
    const int b = blockIdx.x;
    const int tid = threadIdx.x;
    for (int i = tid; i < C_ * T_; i += 256) {
        int c = i & 127, t = i >> 7;
        float v = cb1[c];
        #pragma unroll
        for (int s = 0; s < CSK; s++)
            v += g_y1part[((size_t)s * BT_ + b * T_ + t) * C_ + c];
        ys[c * 26 + t + 1] = fmaxf(v, 0.f);
    }
    if (tid < C_) { ys[tid * 26 + 0] = 0.f; ys[tid * 26 + 25] = 0.f; }
    __syncthreads();

    const int c = tid >> 1;
    const int half = tid & 1;
    const int tbase = half * 12;
    const float bias2 = cb2[c];
    const float* wrow = w2 + c * (C_ * 3);
    float acc[12];
    #pragma unroll
    for (int tt = 0; tt < 12; tt++) acc[tt] = bias2;
    for (int c1 = 0; c1 < C_; c1++) {
        float w0 = wrow[c1 * 3 + 0];
        float w1 = wrow[c1 * 3 + 1];
        float w2v = wrow[c1 * 3 + 2];
        float yv[14];
        #pragma unroll
        for (int idx = 0; idx < 14; idx++) yv[idx] = ys[c1 * 26 + tbase + idx];
        #pragma unroll
        for (int tt = 0; tt < 12; tt++)
            acc[tt] += w0 * yv[tt] + w1 * yv[tt + 1] + w2v * yv[tt + 2];
    }
    float s = 0.f;
    #pragma unroll
    for (int tt = 0; tt < 12; tt++) s += fmaxf(acc[tt], 0.f);
    s += __shfl_xor_sync(0xffffffffu, s, 1);
    if (half == 0) g_pooled[b * C_ + c] = s * (1.f / 24.f);
}

// ---------------- K-E: MLP1 split-K (64 x 19328 x 512), fp32 scalar ----------------
__global__ void k_mlp1(const float* __restrict__ w)
{
    const int n0  = blockIdx.x * 64;
    const int kc0 = blockIdx.y * MLP1_KCH;
    __shared__ float Ast[16][68];
    __shared__ float Bs[16][68];
    const int tid = threadIdx.x;
    const int tx = tid & 15, ty = tid >> 4;
    float acc[4][4] = {};
    for (int k0 = 0; k0 < MLP1_KCH; k0 += 16) {
        for (int i = tid; i < 1024; i += 256) {
            int r = i >> 4, k = i & 15;
            int kg = kc0 + k0 + k;
            float v;
            if (kg < ND_) {
                int nn = kg >> 6, d = kg & 63;   // kg = n*64 + d
                size_t a = ((size_t)((r * T_ + (T_ - 1)) * 64 + d)) * NP + nn;
                v = __bfloat162float(g_Bh[a]) + __bfloat162float(g_Bl[a]);
            } else {
                v = g_pooled[r * C_ + (kg - ND_)];
            }
            Ast[k][r] = v;
        }
        for (int i = tid; i < 1024; i += 256) {
            int k = i >> 6, d = i & 63;
            Bs[k][d] = w[(size_t)(kc0 + k0 + k) * 512 + n0 + d];
        }
        __syncthreads();
        #pragma unroll
        for (int k = 0; k < 16; k++) {
            float4 a4 = *reinterpret_cast<const float4*>(&Ast[k][ty * 4]);
            float4 b4 = *reinterpret_cast<const float4*>(&Bs[k][tx * 4]);
            float a[4] = {a4.x, a4.y, a4.z, a4.w};
            float b[4] = {b4.x, b4.y, b4.z, b4.w};
            #pragma unroll
            for (int i = 0; i < 4; i++)
                #pragma unroll
                for (int j = 0; j < 4; j++) acc[i][j] = fmaf(a[i], b[j], acc[i][j]);
        }
        __syncthreads();
    }
    const int ks = blockIdx.y;
    #pragma unroll
    for (int i = 0; i < 4; i++)
        #pragma unroll
        for (int j = 0; j < 4; j++)
            g_z1part[(ks * B_ + ty * 4 + i) * 512 + n0 + tx * 4 + j] = acc[i][j];
}

// ---------------- K-F: MLP2 ----------------
__global__ void k_mlp2(const float* __restrict__ mb1, const float* __restrict__ w,
                       const float* __restrict__ mb2)
{
    const int n0 = blockIdx.x * 64;
    __shared__ float Ast[16][68];
    __shared__ float Bs[16][68];
    const int tid = threadIdx.x;
    const int tx = tid & 15, ty = tid >> 4;
    float acc[4][4] = {};
    for (int k0 = 0; k0 < 512; k0 += 16) {
        for (int i = tid; i < 1024; i += 256) {
            int r = i >> 4, k = i & 15;
            int kg = k0 + k;
            float v = mb1[kg];
            #pragma unroll
            for (int s = 0; s < MLP1_SK; s++) v += g_z1part[(s * B_ + r) * 512 + kg];
            Ast[k][r] = fmaxf(v, 0.f);
        }
        for (int i = tid; i < 1024; i += 256) {
            int k = i >> 6, d = i & 63;
            Bs[k][d] = w[(k0 + k) * 256 + n0 + d];
        }
        __syncthreads();
        #pragma unroll
        for (int k = 0; k < 16; k++) {
            float4 a4 = *reinterpret_cast<const float4*>(&Ast[k][ty * 4]);
            float4 b4 = *reinterpret_cast<const float4*>(&Bs[k][tx * 4]);
            float a[4] = {a4.x, a4.y, a4.z, a4.w};
            float b[4] = {b4.x, b4.y, b4.z, b4.w};
            #pragma unroll
            for (int i = 0; i < 4; i++)
                #pragma unroll
                for (int j = 0; j < 4; j++) acc[i][j] = fmaf(a[i], b[j], acc[i][j]);
        }
        __syncthreads();
    }
    #pragma unroll
    for (int i = 0; i < 4; i++)
        #pragma unroll
        for (int j = 0; j < 4; j++) {
            int n = n0 + tx * 4 + j;
            g_z2[(ty * 4 + i) * 256 + n] = fmaxf(acc[i][j] + mb2[n], 0.f);
        }
}

// ---------------- K-G: MLP3 -> d_out ----------------
__global__ void k_mlp3(const float* __restrict__ w, const float* __restrict__ mb3,
                       float* __restrict__ out)
{
    const int n0 = blockIdx.x * 64;
    __shared__ float Ast[16][68];
    __shared__ float Bs[16][68];
    const int tid = threadIdx.x;
    const int tx = tid & 15, ty = tid >> 4;
    float acc[4][4] = {};
    for (int k0 = 0; k0 < 256; k0 += 16) {
        for (int i = tid; i < 1024; i += 256) {
            int r = i >> 4, k = i & 15;
            Ast[k][r] = g_z2[r * 256 + k0 + k];
        }
        for (int i = tid; i < 1024; i += 256) {
            int k = i >> 6, d = i & 63;
            int n = n0 + d;
            Bs[k][d] = (n < N_ * H_) ? w[(k0 + k) * (N_ * H_) + n] : 0.f;
        }
        __syncthreads();
        #pragma unroll
        for (int k = 0; k < 16; k++) {
            float4 a4 = *reinterpret_cast<const float4*>(&Ast[k][ty * 4]);
            float4 b4 = *reinterpret_cast<const float4*>(&Bs[k][tx * 4]);
            float a[4] = {a4.x, a4.y, a4.z, a4.w};
            float b[4] = {b4.x, b4.y, b4.z, b4.w};
            #pragma unroll
            for (int i = 0; i < 4; i++)
                #pragma unroll
                for (int j = 0; j < 4; j++) acc[i][j] = fmaf(a[i], b[j], acc[i][j]);
        }
        __syncthreads();
    }
    #pragma unroll
    for (int i = 0; i < 4; i++)
        #pragma unroll
        for (int j = 0; j < 4; j++) {
            int n = n0 + tx * 4 + j;
            if (n < N_ * H_)
                out[(ty * 4 + i) * (N_ * H_) + n] = acc[i][j] + mb3[n];
        }
}

// ---------------- launch ----------------
extern "C" void kernel_launch(void* const* d_in, const int* in_sizes, int n_in,
                              void* d_out, int out_size)
{
    const float* x    = (const float*)d_in[0];
    const float* adj  = (const float*)d_in[1];
    const float* gw1  = (const float*)d_in[2];
    const float* gb1  = (const float*)d_in[3];
    const float* gw2  = (const float*)d_in[4];
    const float* gb2  = (const float*)d_in[5];
    const float* cw1  = (const float*)d_in[6];
    const float* cb1  = (const float*)d_in[7];
    const float* cw2  = (const float*)d_in[8];
    const float* cb2  = (const float*)d_in[9];
    const float* mw1  = (const float*)d_in[10];
    const float* mb1  = (const float*)d_in[11];
    const float* mw2  = (const float*)d_in[12];
    const float* mb2  = (const float*)d_in[13];
    const float* mw3  = (const float*)d_in[14];
    const float* mb3  = (const float*)d_in[15];
    float* out = (float*)d_out;

    bf16 *Ah, *Al, *Bh, *Bl;
    cudaGetSymbolAddress((void**)&Ah, g_Ah);
    cudaGetSymbolAddress((void**)&Al, g_Al);
    cudaGetSymbolAddress((void**)&Bh, g_Bh);
    cudaGetSymbolAddress((void**)&Bl, g_Bl);

    k_prep<<<(300 * NP + 4096 + 255) / 256, 256>>>(adj, gw2);
    k_repack<<<dim3(C_, 6), 256>>>(cw1);
    k_xw1<<<BTN_ / 64, 256>>>(x, gw1);                        // S1 -> A (split)
    k_adjmm<<<dim3(Q_ / 128, 3), 256>>>(Ah, Al, gb1, Bh, Bl); // h1 -> B
    k_hw2mma<<<BTN_ / 64, 256>>>();                           // S2 -> A
    k_adjmm<<<dim3(Q_ / 128, 3), 256>>>(Ah, Al, gb2, Bh, Bl); // h2 -> B
    k_conv1<<<dim3(BT_ / 128, CSK), 256>>>();
    k_conv2pool<<<B_, 256>>>(cb1, cw2, cb2);
    k_mlp1<<<dim3(512 / 64, MLP1_SK), 256>>>(mw1);
    k_mlp2<<<256 / 64, 256>>>(mb1, mw2, mb2);
    k_mlp3<<<(N_ * H_ + 63) / 64, 256>>>(mw3, mb3, out);
}